// round 11
// baseline (speedup 1.0000x reference)
#include <cuda_runtime.h>
#include <cuda_fp16.h>
#include <math.h>
#include <stdint.h>

#define NN 200000
#define EE 1000000
#define INF 128
#define OUTF 128
#define HH 4
#define DKK 32
#define TILES 1563            // ceil(NN/128)

// smem layout (bytes): rows padded to 272B (conflict-free LDSM)
#define ROWB 272
#define A_HI_OFF 0
#define A_LO_OFF 34816
#define PROJ_B_OFF 34816      // proj: 1-term, B right after A_HI
#define NODE_B_OFF 69632      // node: 2-term, B after A_HI+A_LO
#define SMEM_PROJ 69632
#define SMEM_NODE 104448

// ---------------- scratch (device globals; no allocation) ----------------
__device__ __half g_KMh[(size_t)2*NN*2*OUTF];   // K/M interleaved fp16: [2N][2][128]
__device__ __half g_Qh [(size_t)2*NN*OUTF];     // fp16
__device__ float  g_WkA[2*INF*OUTF];
__device__ float  g_bkA[2*OUTF];
__device__ float  g_WmM[2*INF*OUTF];
__device__ float  g_bmM[2*OUTF];
// packed fp16 weights, W^T layout [o][k]: [mat(4)][type(2)][128*128]
__device__ __half g_Wh[(size_t)4*2*16384];
// exact-dst sorted edges: srcs only, grouped by destination node (d-major)
__device__ uint32_t g_srt[(size_t)2*EE];
__device__ int    g_hist[2*NN];
__device__ int    g_cursor[2*NN + 1];
__device__ int    g_cur2[2*NN];
__device__ int    g_bsum[512];
__device__ int    g_bsumx[512];

#define MMA16816F16(acc, A0,A1,A2,A3, B0,B1) \
  asm volatile("mma.sync.aligned.m16n8k16.row.col.f32.f16.f16.f32 " \
    "{%0,%1,%2,%3}, {%4,%5,%6,%7}, {%8,%9}, {%0,%1,%2,%3};" \
    : "+f"((acc)[0]), "+f"((acc)[1]), "+f"((acc)[2]), "+f"((acc)[3]) \
    : "r"(A0), "r"(A1), "r"(A2), "r"(A3), "r"(B0), "r"(B1))

#define LDSM4(r0,r1,r2,r3,addr) \
  asm volatile("ldmatrix.sync.aligned.m8n8.x4.shared.b16 {%0,%1,%2,%3}, [%4];" \
    : "=r"(r0), "=r"(r1), "=r"(r2), "=r"(r3) : "r"(addr))

__device__ __forceinline__ uint32_t smem_u32(const void* p) {
    uint32_t a;
    asm("{ .reg .u64 t; cvta.to.shared.u64 t, %1; cvt.u32.u64 %0, t; }" : "=r"(a) : "l"(p));
    return a;
}

// ---------------- prep: fold w_att/w_msg (+ mu*scale) into projection weights
__global__ void prep_fold(const float* __restrict__ Wk, const float* __restrict__ bk,
                          const float* __restrict__ Wm, const float* __restrict__ bm,
                          const float* __restrict__ w_att, const float* __restrict__ w_msg,
                          const float* __restrict__ mu) {
    int idx = blockIdx.x*blockDim.x + threadIdx.x;     // 65536
    const int total = 2*INF*OUTF;
    int m   = idx / total;
    int rem = idx - m*total;
    int t   = rem / (INF*OUTF);
    int io  = rem - t*(INF*OUTF);
    int i   = io / OUTF;
    int o   = io - i*OUTF;
    int h   = o >> 5, f = o & 31;

    const float* W = m ? Wm : Wk;
    const float* R = m ? w_msg : w_att;
    const float* wrow = W + ((size_t)t*INF + i)*OUTF + h*DKK;
    const float* rr   = R + (((size_t)t*HH + h)*DKK)*DKK + f;
    float s = 0.f;
    #pragma unroll
    for (int d = 0; d < DKK; d++) s += wrow[d] * rr[(size_t)d*DKK];
    float fold = m ? 1.f : mu[t*HH + h] * 0.17677669529663687f;   // mu / sqrt(DK)
    (m ? g_WmM : g_WkA)[(size_t)t*INF*OUTF + io] = s * fold;

    if (i == 0) {
        const float* b = m ? bm : bk;
        float sb = 0.f;
        #pragma unroll
        for (int d = 0; d < DKK; d++) sb += b[t*OUTF + h*DKK + d] * rr[(size_t)d*DKK];
        (m ? g_bmM : g_bkA)[t*OUTF + o] = sb * fold;
    }
}

// pack 4 matrices (Kfold, Mfold, Q, A) per type as W^T [o][k] fp16
__global__ void prep_pack(const float* __restrict__ Wq, const float* __restrict__ Wa) {
    int idx = blockIdx.x*blockDim.x + threadIdx.x;   // 131072
    int mat = idx >> 15;
    int rem = idx & 32767;
    int t   = rem >> 14;
    int ok  = rem & 16383;
    int o   = ok >> 7;
    int k   = ok & 127;
    const float* W = (mat==0) ? g_WkA : (mat==1) ? g_WmM : (mat==2) ? Wq : Wa;
    float v = W[((size_t)t*INF + k)*OUTF + o];
    g_Wh[(size_t)(mat*2 + t)*16384 + ok] = __float2half(v);
}

// ---------------- zero per-dst histogram ----------------
__global__ void zero_hist() {
    int i = blockIdx.x*blockDim.x + threadIdx.x;
    if (i < 2*NN) g_hist[i] = 0;
}

// ---------------- exact-dst bucketing: histogram -> 2-level scan -> scatter ----
__global__ void hist_kernel(const int* __restrict__ ei) {
    int i = blockIdx.x*blockDim.x + threadIdx.x;
    if (i >= 2*EE) return;
    int t = i >= EE;
    int e = i - t*EE;
    int dst = ei[(size_t)t*2*EE + EE + e];
    atomicAdd(&g_hist[(1-t)*NN + dst], 1);     // node key = d*NN + dst
}

__global__ void scan_blocks() {                // 391 blocks x 1024
    __shared__ int ss[1024];
    int tid = threadIdx.x;
    int gi = blockIdx.x*1024 + tid;
    int v = (gi < 2*NN) ? g_hist[gi] : 0;
    ss[tid] = v;
    __syncthreads();
    for (int off = 1; off < 1024; off <<= 1) {
        int u = (tid >= off) ? ss[tid-off] : 0;
        __syncthreads();
        ss[tid] += u;
        __syncthreads();
    }
    if (gi < 2*NN) g_cursor[gi] = ss[tid] - v;   // exclusive within block
    if (tid == 1023) g_bsum[blockIdx.x] = ss[1023];
}

__global__ void scan_tops() {                  // 1 block x 512 (covers 391 block sums)
    __shared__ int ss[512];
    int tid = threadIdx.x;
    int v = (tid < 391) ? g_bsum[tid] : 0;
    ss[tid] = v;
    __syncthreads();
    for (int off = 1; off < 512; off <<= 1) {
        int u = (tid >= off) ? ss[tid-off] : 0;
        __syncthreads();
        ss[tid] += u;
        __syncthreads();
    }
    g_bsumx[tid] = ss[tid] - v;                // exclusive
}

__global__ void add_offs() {                   // 391 blocks x 1024
    int tid = threadIdx.x;
    int gi = blockIdx.x*1024 + tid;
    if (gi < 2*NN) {
        int c = g_cursor[gi] + g_bsumx[blockIdx.x];
        g_cursor[gi] = c;
        g_cur2[gi]   = c;
    }
    if (gi == 0) g_cursor[2*NN] = 2*EE;
}

__global__ void scatter_kernel(const int* __restrict__ ei) {
    int i = blockIdx.x*blockDim.x + threadIdx.x;
    if (i >= 2*EE) return;
    int t = i >= EE;
    int e = i - t*EE;
    int src = ei[(size_t)t*2*EE + e];
    int dst = ei[(size_t)t*2*EE + EE + e];
    int pos = atomicAdd(&g_cur2[(1-t)*NN + dst], 1);
    g_srt[pos] = (uint32_t)src;
}

// split float4 -> two fp16x2 hi words + two fp16x2 lo (residual) words
__device__ __forceinline__ void split4h(float4 v, uint32_t* hi2, uint32_t* lo2) {
    __half2 h01 = __floats2half2_rn(v.x, v.y);
    __half2 h23 = __floats2half2_rn(v.z, v.w);
    __half2 l01 = __floats2half2_rn(v.x - __half2float(__low2half(h01)),
                                    v.y - __half2float(__high2half(h01)));
    __half2 l23 = __floats2half2_rn(v.z - __half2float(__low2half(h23)),
                                    v.w - __half2float(__high2half(h23)));
    hi2[0] = *reinterpret_cast<uint32_t*>(&h01);
    hi2[1] = *reinterpret_cast<uint32_t*>(&h23);
    lo2[0] = *reinterpret_cast<uint32_t*>(&l01);
    lo2[1] = *reinterpret_cast<uint32_t*>(&l23);
}

// copy one packed fp16 weight matrix (32KB) into the padded B buffer at b_off
__device__ __forceinline__ void copy_B(char* sm, uint32_t b_off, int mat, int nt, int tid) {
    const uint4* src = (const uint4*)(g_Wh + (size_t)(mat*2 + nt) * 16384);
    #pragma unroll 2
    for (int i = tid; i < 2048; i += 256) {
        int row = i >> 4, chunk = i & 15;
        *(uint4*)(sm + b_off + row*ROWB + chunk*16) = src[i];
    }
}

// 1-term fp16 GEMM: acc += Ah*B
__device__ __forceinline__ void gemm_1term(uint32_t su, int w, int lane, float acc[2][8][4]) {
    int wm = w & 3, wn = w >> 2;
    int mat = lane >> 3, r8 = lane & 7;
    uint32_t aoff = (uint32_t)(wm*32 + (mat&1)*8 + r8)*ROWB + (mat>>1)*16;
    uint32_t boff = (uint32_t)(wn*64 + (mat>>1)*8 + r8)*ROWB + (mat&1)*16 + PROJ_B_OFF;

    #pragma unroll
    for (int kk = 0; kk < 8; kk++) {
        uint32_t kb = kk*32;
        uint32_t A[2][4], B[8][2];
        #pragma unroll
        for (int mt = 0; mt < 2; mt++) {
            uint32_t ao = aoff + mt*16*ROWB + kb;
            LDSM4(A[mt][0], A[mt][1], A[mt][2], A[mt][3], su + A_HI_OFF + ao);
        }
        #pragma unroll
        for (int p = 0; p < 4; p++) {
            uint32_t bo = boff + p*16*ROWB + kb;
            LDSM4(B[2*p][0], B[2*p][1], B[2*p+1][0], B[2*p+1][1], su + bo);
        }
        #pragma unroll
        for (int mt = 0; mt < 2; mt++)
            #pragma unroll
            for (int nt = 0; nt < 8; nt++)
                MMA16816F16(acc[mt][nt], A[mt][0],A[mt][1],A[mt][2],A[mt][3], B[nt][0],B[nt][1]);
    }
}

// 2-term fp16 GEMM: acc += Ah*B + Al*B  (A = Ah+Al exact, B single-rounded fp16)
__device__ __forceinline__ void gemm_2term(uint32_t su, int w, int lane, float acc[2][8][4]) {
    int wm = w & 3, wn = w >> 2;
    int mat = lane >> 3, r8 = lane & 7;
    uint32_t aoff = (uint32_t)(wm*32 + (mat&1)*8 + r8)*ROWB + (mat>>1)*16;
    uint32_t boff = (uint32_t)(wn*64 + (mat>>1)*8 + r8)*ROWB + (mat&1)*16 + NODE_B_OFF;

    #pragma unroll
    for (int kk = 0; kk < 8; kk++) {
        uint32_t kb = kk*32;
        uint32_t Ah[2][4], Al[2][4], B[8][2];
        #pragma unroll
        for (int mt = 0; mt < 2; mt++) {
            uint32_t ao = aoff + mt*16*ROWB + kb;
            LDSM4(Ah[mt][0], Ah[mt][1], Ah[mt][2], Ah[mt][3], su + A_HI_OFF + ao);
            LDSM4(Al[mt][0], Al[mt][1], Al[mt][2], Al[mt][3], su + A_LO_OFF + ao);
        }
        #pragma unroll
        for (int p = 0; p < 4; p++) {
            uint32_t bo = boff + p*16*ROWB + kb;
            LDSM4(B[2*p][0], B[2*p][1], B[2*p+1][0], B[2*p+1][1], su + bo);
        }
        #pragma unroll
        for (int mt = 0; mt < 2; mt++)
            #pragma unroll
            for (int nt = 0; nt < 8; nt++) {
                MMA16816F16(acc[mt][nt], Ah[mt][0],Ah[mt][1],Ah[mt][2],Ah[mt][3], B[nt][0],B[nt][1]);
                MMA16816F16(acc[mt][nt], Al[mt][0],Al[mt][1],Al[mt][2],Al[mt][3], B[nt][0],B[nt][1]);
            }
    }
}

// ---------------- proj: Ktr, Mtr, Q via 1-term mma.sync -> fp16 tables ----------------
__global__ void __launch_bounds__(256, 2) proj_mma_kernel(const float* __restrict__ x,
                                                          const float* __restrict__ bq) {
    extern __shared__ char sm[];
    uint32_t su = smem_u32(sm);
    int tid = threadIdx.x;
    int w = tid >> 5, lane = tid & 31;
    int wm = w & 3, wn = w >> 2;

    int blk = blockIdx.x;
    int ntp = blk >= TILES;
    int tb  = blk - ntp*TILES;
    int base = tb*128; if (base > NN-128) base = NN-128;
    size_t nbase = (size_t)ntp*NN + base;

    // stage A: x rows -> fp16 smem (single-rounded)
    #pragma unroll 4
    for (int j = 0; j < 16; j++) {
        int idx = tid + j*256;             // 4096 float4
        int row = idx >> 5, c4 = idx & 31;
        float4 v = ((const float4*)(x + (nbase + row)*INF))[c4];
        __half2 h01 = __floats2half2_rn(v.x, v.y);
        __half2 h23 = __floats2half2_rn(v.z, v.w);
        *(uint32_t*)(sm + A_HI_OFF + row*ROWB + c4*8)     = *reinterpret_cast<uint32_t*>(&h01);
        *(uint32_t*)(sm + A_HI_OFF + row*ROWB + c4*8 + 4) = *reinterpret_cast<uint32_t*>(&h23);
    }

    for (int m = 0; m < 3; m++) {
        __syncthreads();
        copy_B(sm, PROJ_B_OFF, m, ntp, tid);
        __syncthreads();

        const float* bias = (m==0) ? g_bkA + ntp*OUTF
                          : (m==1) ? g_bmM + ntp*OUTF
                                   : bq    + ntp*OUTF;
        float acc[2][8][4];
        #pragma unroll
        for (int mt = 0; mt < 2; mt++)
            #pragma unroll
            for (int nt = 0; nt < 8; nt++) {
                int col = wn*64 + nt*8 + 2*(lane & 3);
                float b0 = bias[col], b1 = bias[col+1];
                acc[mt][nt][0] = b0; acc[mt][nt][1] = b1;
                acc[mt][nt][2] = b0; acc[mt][nt][3] = b1;
            }
        gemm_1term(su, w, lane, acc);
        __syncthreads();   // all warps done with B before staging reuses it

        // stage fp16 result into B buffer: 128 rows x 256B (+ ROWB pad)
        __half* H = (__half*)(sm + PROJ_B_OFF);
        #pragma unroll
        for (int mt = 0; mt < 2; mt++)
            #pragma unroll
            for (int nt = 0; nt < 8; nt++) {
                int row = wm*32 + mt*16 + (lane >> 2);
                int col = wn*64 + nt*8 + 2*(lane & 3);
                *(__half2*)((char*)H + row*ROWB + col*2) =
                    __floats2half2_rn(acc[mt][nt][0], acc[mt][nt][1]);
                *(__half2*)((char*)H + (row+8)*ROWB + col*2) =
                    __floats2half2_rn(acc[mt][nt][2], acc[mt][nt][3]);
            }
        __syncthreads();

        // coalesced copy-out: 128 rows x 256B
        #pragma unroll
        for (int i = tid; i < 2048; i += 256) {
            int row = i >> 4, ch = i & 15;
            uint4 v = *(uint4*)((char*)H + row*ROWB + ch*16);
            __half* dst = (m == 2) ? g_Qh + (nbase + row)*OUTF + ch*8
                                   : g_KMh + ((nbase + row)*2 + m)*OUTF + ch*8;
            *(uint4*)dst = v;
        }
    }
}

// ---- fused: per-warp edge aggregation -> smem A (fp16 hi/lo) -> GEMM -> skip+LN ----
__global__ void __launch_bounds__(256, 2) fused_node_kernel(const float* __restrict__ x,
                                                            const float* __restrict__ ba,
                                                            const float* __restrict__ skip,
                                                            const float* __restrict__ lns,
                                                            const float* __restrict__ lnb,
                                                            float* __restrict__ out) {
    extern __shared__ char sm[];
    uint32_t su = smem_u32(sm);
    float* S = (float*)sm;        // reuse A hi/lo region after GEMM: [128][136] f32
    int tid = threadIdx.x;
    int w = tid >> 5, lane = tid & 31;
    int wm = w & 3, wn = w >> 2;

    int blk = blockIdx.x;
    int ntp = blk >= TILES;
    int tb  = blk - ntp*TILES;
    int base = tb*128; if (base > NN-128) base = NN-128;
    size_t nbase = (size_t)ntp*NN + base;
    int s = 1 - ntp;

    // ---- phase 1: warp w aggregates nodes w*16 .. w*16+15, writes gelu'd A to smem
    for (int j = 0; j < 16; j++) {
        int row = w*16 + j;
        size_t node = nbase + row;           // global table index (d-major: d == ntp)
        int start = g_cursor[node];
        int end   = g_cursor[node + 1];

        float4 acc = make_float4(0.f, 0.f, 0.f, 0.f);
        float den = 0.f;

        if (start < end) {
            uint2 qv = ((const uint2*)(g_Qh + node*(size_t)OUTF))[lane];
            float2 qa = __half22float2(*(const __half2*)&qv.x);
            float2 qb = __half22float2(*(const __half2*)&qv.y);

            uint2 kv0, mv0;
            {
                int sc = (int)g_srt[start];
                const uint2* km = (const uint2*)(g_KMh + (size_t)(s*NN + sc)*2*OUTF);
                kv0 = km[lane]; mv0 = km[32 + lane];
            }
            for (int i = start; i < end; i++) {
                uint2 kv = kv0, mv = mv0;
                if (i + 1 < end) {
                    int sc = (int)g_srt[i + 1];
                    const uint2* km = (const uint2*)(g_KMh + (size_t)(s*NN + sc)*2*OUTF);
                    kv0 = km[lane]; mv0 = km[32 + lane];
                }
                float2 ka = __half22float2(*(const __half2*)&kv.x);
                float2 kb = __half22float2(*(const __half2*)&kv.y);
                float p = ka.x*qa.x + ka.y*qa.y + kb.x*qb.x + kb.y*qb.y;
                p += __shfl_down_sync(0xffffffffu, p, 4, 8);
                p += __shfl_down_sync(0xffffffffu, p, 2, 8);
                p += __shfl_down_sync(0xffffffffu, p, 1, 8);
                float att = __shfl_sync(0xffffffffu, p, 0, 8);
                float ev  = __expf(att);

                float2 ma = __half22float2(*(const __half2*)&mv.x);
                float2 mb = __half22float2(*(const __half2*)&mv.y);
                acc.x += ma.x*ev; acc.y += ma.y*ev;
                acc.z += mb.x*ev; acc.w += mb.y*ev;
                den += ev;
            }
        }

        // softmax normalize + exact gelu + fp16 hi/lo split -> smem A row
        float idn = 1.f / (den + 1e-16f);
        float4 v;
        v.x = acc.x*idn; v.y = acc.y*idn; v.z = acc.z*idn; v.w = acc.w*idn;
        v.x = 0.5f*v.x*(1.f + erff(v.x*0.70710678118654752f));
        v.y = 0.5f*v.y*(1.f + erff(v.y*0.70710678118654752f));
        v.z = 0.5f*v.z*(1.f + erff(v.z*0.70710678118654752f));
        v.w = 0.5f*v.w*(1.f + erff(v.w*0.70710678118654752f));
        uint32_t hi[2], lo[2];
        split4h(v, hi, lo);
        *(uint32_t*)(sm + A_HI_OFF + row*ROWB + lane*8)     = hi[0];
        *(uint32_t*)(sm + A_HI_OFF + row*ROWB + lane*8 + 4) = hi[1];
        *(uint32_t*)(sm + A_LO_OFF + row*ROWB + lane*8)     = lo[0];
        *(uint32_t*)(sm + A_LO_OFF + row*ROWB + lane*8 + 4) = lo[1];
    }
    __syncthreads();

    // ---- phase 2: Wa GEMM (2-term) + skip blend + layernorm
    copy_B(sm, NODE_B_OFF, 3, ntp, tid);
    __syncthreads();

    float acc[2][8][4];
    #pragma unroll
    for (int mt = 0; mt < 2; mt++)
        #pragma unroll
        for (int nt = 0; nt < 8; nt++) {
            int col = wn*64 + nt*8 + 2*(lane & 3);
            float b0 = ba[ntp*OUTF + col], b1 = ba[ntp*OUTF + col + 1];
            acc[mt][nt][0] = b0; acc[mt][nt][1] = b1;
            acc[mt][nt][2] = b0; acc[mt][nt][3] = b1;
        }
    gemm_2term(su, w, lane, acc);
    __syncthreads();   // all warps done reading A region before reuse as S

    // acc -> S [128][136] f32
    #pragma unroll
    for (int mt = 0; mt < 2; mt++)
        #pragma unroll
        for (int nt = 0; nt < 8; nt++) {
            int row = wm*32 + mt*16 + (lane >> 2);
            int col = wn*64 + nt*8 + 2*(lane & 3);
            *(float2*)(S + row*136 + col)     = make_float2(acc[mt][nt][0], acc[mt][nt][1]);
            *(float2*)(S + (row+8)*136 + col) = make_float2(acc[mt][nt][2], acc[mt][nt][3]);
        }
    __syncthreads();

    // skip blend
    float alpha = 1.f / (1.f + __expf(-skip[ntp]));
    float beta  = 1.f - alpha;
    #pragma unroll 4
    for (int i = tid; i < 128*128; i += 256) {
        int r = i >> 7, c = i & 127;
        S[r*136 + c] = alpha*S[r*136 + c] + beta*x[(nbase + r)*INF + c];
    }
    __syncthreads();

    // layernorm: warp w rows 16w..16w+15
    for (int rr = 0; rr < 16; rr++) {
        int r = w*16 + rr;
        float s1 = 0.f, s2 = 0.f;
        #pragma unroll
        for (int c = lane; c < OUTF; c += 32) { float v = S[r*136 + c]; s1 += v; s2 += v*v; }
        #pragma unroll
        for (int off = 16; off; off >>= 1) {
            s1 += __shfl_xor_sync(0xffffffffu, s1, off);
            s2 += __shfl_xor_sync(0xffffffffu, s2, off);
        }
        float mean = s1 * (1.f/OUTF);
        float var  = s2 * (1.f/OUTF) - mean*mean;
        float inv  = rsqrtf(var + 1e-5f);
        #pragma unroll
        for (int c = lane; c < OUTF; c += 32)
            out[(nbase + r)*OUTF + c] = (S[r*136 + c] - mean)*inv*lns[ntp*OUTF + c]
                                        + lnb[ntp*OUTF + c];
    }
}

// ---------------- launch ----------------
extern "C" void kernel_launch(void* const* d_in, const int* in_sizes, int n_in,
                              void* d_out, int out_size) {
    const float* x     = (const float*)d_in[0];
    const int*   ei    = (const int*)  d_in[1];
    const float* Wk    = (const float*)d_in[2];
    const float* bk    = (const float*)d_in[3];
    const float* Wq    = (const float*)d_in[4];
    const float* bq    = (const float*)d_in[5];
    const float* Wm    = (const float*)d_in[6];
    const float* bm    = (const float*)d_in[7];
    const float* Wa    = (const float*)d_in[8];
    const float* ba    = (const float*)d_in[9];
    const float* w_att = (const float*)d_in[10];
    const float* w_msg = (const float*)d_in[11];
    const float* mu    = (const float*)d_in[12];
    const float* skip  = (const float*)d_in[13];
    const float* lns   = (const float*)d_in[14];
    const float* lnb   = (const float*)d_in[15];
    float* out = (float*)d_out;

    cudaFuncSetAttribute(proj_mma_kernel, cudaFuncAttributeMaxDynamicSharedMemorySize, SMEM_PROJ);
    cudaFuncSetAttribute(fused_node_kernel, cudaFuncAttributeMaxDynamicSharedMemorySize, SMEM_NODE);

    prep_fold<<<256, 256>>>(Wk, bk, Wm, bm, w_att, w_msg, mu);
    prep_pack<<<512, 256>>>(Wq, Wa);
    zero_hist<<<(2*NN + 255)/256, 256>>>();
    hist_kernel<<<(2*EE + 255)/256, 256>>>(ei);
    scan_blocks<<<(2*NN + 1023)/1024, 1024>>>();
    scan_tops<<<1, 512>>>();
    add_offs<<<(2*NN + 1023)/1024, 1024>>>();
    scatter_kernel<<<(2*EE + 255)/256, 256>>>(ei);
    proj_mma_kernel<<<2*TILES, 256, SMEM_PROJ>>>(x, bq);
    fused_node_kernel<<<2*TILES, 256, SMEM_NODE>>>(x, ba, skip, lns, lnb, out);
}

// round 12
// speedup vs baseline: 1.1485x; 1.1485x over previous
#include <cuda_runtime.h>
#include <cuda_fp16.h>
#include <math.h>
#include <stdint.h>

#define NN 200000
#define EE 1000000
#define INF 128
#define OUTF 128
#define HH 4
#define DKK 32
#define TILES 1563            // ceil(NN/128)

// smem layout (bytes): rows padded to 272B (conflict-free LDSM)
#define ROWB 272
#define A_HI_OFF 0
#define A_LO_OFF 34816
#define PROJ_B_OFF 34816      // proj: 1-term, B right after A_HI
#define NODE_B_OFF 69632      // node: 2-term, B after A_HI+A_LO
#define SMEM_PROJ 69632
#define SMEM_NODE 104448

// ---------------- scratch (device globals; no allocation) ----------------
__device__ __half g_KMh[(size_t)2*NN*2*OUTF];   // K/M interleaved fp16: [2N][2][128]
__device__ __half g_Qh [(size_t)2*NN*OUTF];     // fp16
__device__ float  g_agg[(size_t)2*NN*OUTF];
__device__ float  g_den[(size_t)2*NN*HH];
__device__ float  g_WkA[2*INF*OUTF];
__device__ float  g_bkA[2*OUTF];
__device__ float  g_WmM[2*INF*OUTF];
__device__ float  g_bmM[2*OUTF];
// packed fp16 weights, W^T layout [o][k]: [mat(4)][type(2)][128*128]
__device__ __half g_Wh[(size_t)4*2*16384];
// exact-dst sorted edges: srcs only, grouped by destination node (d-major)
__device__ uint32_t g_srt[(size_t)2*EE];
__device__ int    g_hist[2*NN];
__device__ int    g_cursor[2*NN + 1];
__device__ int    g_cur2[2*NN];
__device__ int    g_bsum[512];
__device__ int    g_bsumx[512];

#define MMA16816F16(acc, A0,A1,A2,A3, B0,B1) \
  asm volatile("mma.sync.aligned.m16n8k16.row.col.f32.f16.f16.f32 " \
    "{%0,%1,%2,%3}, {%4,%5,%6,%7}, {%8,%9}, {%0,%1,%2,%3};" \
    : "+f"((acc)[0]), "+f"((acc)[1]), "+f"((acc)[2]), "+f"((acc)[3]) \
    : "r"(A0), "r"(A1), "r"(A2), "r"(A3), "r"(B0), "r"(B1))

#define LDSM4(r0,r1,r2,r3,addr) \
  asm volatile("ldmatrix.sync.aligned.m8n8.x4.shared.b16 {%0,%1,%2,%3}, [%4];" \
    : "=r"(r0), "=r"(r1), "=r"(r2), "=r"(r3) : "r"(addr))

__device__ __forceinline__ uint32_t smem_u32(const void* p) {
    uint32_t a;
    asm("{ .reg .u64 t; cvta.to.shared.u64 t, %1; cvt.u32.u64 %0, t; }" : "=r"(a) : "l"(p));
    return a;
}

// ---------------- prep: fold w_att/w_msg (+ mu*scale) into projection weights
__global__ void prep_fold(const float* __restrict__ Wk, const float* __restrict__ bk,
                          const float* __restrict__ Wm, const float* __restrict__ bm,
                          const float* __restrict__ w_att, const float* __restrict__ w_msg,
                          const float* __restrict__ mu) {
    int idx = blockIdx.x*blockDim.x + threadIdx.x;     // 65536
    const int total = 2*INF*OUTF;
    int m   = idx / total;
    int rem = idx - m*total;
    int t   = rem / (INF*OUTF);
    int io  = rem - t*(INF*OUTF);
    int i   = io / OUTF;
    int o   = io - i*OUTF;
    int h   = o >> 5, f = o & 31;

    const float* W = m ? Wm : Wk;
    const float* R = m ? w_msg : w_att;
    const float* wrow = W + ((size_t)t*INF + i)*OUTF + h*DKK;
    const float* rr   = R + (((size_t)t*HH + h)*DKK)*DKK + f;
    float s = 0.f;
    #pragma unroll
    for (int d = 0; d < DKK; d++) s += wrow[d] * rr[(size_t)d*DKK];
    float fold = m ? 1.f : mu[t*HH + h] * 0.17677669529663687f;   // mu / sqrt(DK)
    (m ? g_WmM : g_WkA)[(size_t)t*INF*OUTF + io] = s * fold;

    if (i == 0) {
        const float* b = m ? bm : bk;
        float sb = 0.f;
        #pragma unroll
        for (int d = 0; d < DKK; d++) sb += b[t*OUTF + h*DKK + d] * rr[(size_t)d*DKK];
        (m ? g_bmM : g_bkA)[t*OUTF + o] = sb * fold;
    }
}

// pack 4 matrices (Kfold, Mfold, Q, A) per type as W^T [o][k] fp16
__global__ void prep_pack(const float* __restrict__ Wq, const float* __restrict__ Wa) {
    int idx = blockIdx.x*blockDim.x + threadIdx.x;   // 131072
    int mat = idx >> 15;
    int rem = idx & 32767;
    int t   = rem >> 14;
    int ok  = rem & 16383;
    int o   = ok >> 7;
    int k   = ok & 127;
    const float* W = (mat==0) ? g_WkA : (mat==1) ? g_WmM : (mat==2) ? Wq : Wa;
    float v = W[((size_t)t*INF + k)*OUTF + o];
    g_Wh[(size_t)(mat*2 + t)*16384 + ok] = __float2half(v);
}

// ---------------- zero per-dst histogram ----------------
__global__ void zero_hist() {
    int i = blockIdx.x*blockDim.x + threadIdx.x;
    if (i < 2*NN) g_hist[i] = 0;
}

// ---------------- exact-dst bucketing: histogram -> 2-level scan -> scatter ----
__global__ void hist_kernel(const int* __restrict__ ei) {
    int i = blockIdx.x*blockDim.x + threadIdx.x;
    if (i >= 2*EE) return;
    int t = i >= EE;
    int e = i - t*EE;
    int dst = ei[(size_t)t*2*EE + EE + e];
    atomicAdd(&g_hist[(1-t)*NN + dst], 1);     // node key = d*NN + dst
}

__global__ void scan_blocks() {                // 391 blocks x 1024
    __shared__ int ss[1024];
    int tid = threadIdx.x;
    int gi = blockIdx.x*1024 + tid;
    int v = (gi < 2*NN) ? g_hist[gi] : 0;
    ss[tid] = v;
    __syncthreads();
    for (int off = 1; off < 1024; off <<= 1) {
        int u = (tid >= off) ? ss[tid-off] : 0;
        __syncthreads();
        ss[tid] += u;
        __syncthreads();
    }
    if (gi < 2*NN) g_cursor[gi] = ss[tid] - v;   // exclusive within block
    if (tid == 1023) g_bsum[blockIdx.x] = ss[1023];
}

__global__ void scan_tops() {                  // 1 block x 512 (covers 391 block sums)
    __shared__ int ss[512];
    int tid = threadIdx.x;
    int v = (tid < 391) ? g_bsum[tid] : 0;
    ss[tid] = v;
    __syncthreads();
    for (int off = 1; off < 512; off <<= 1) {
        int u = (tid >= off) ? ss[tid-off] : 0;
        __syncthreads();
        ss[tid] += u;
        __syncthreads();
    }
    g_bsumx[tid] = ss[tid] - v;                // exclusive
}

__global__ void add_offs() {                   // 391 blocks x 1024
    int tid = threadIdx.x;
    int gi = blockIdx.x*1024 + tid;
    if (gi < 2*NN) {
        int c = g_cursor[gi] + g_bsumx[blockIdx.x];
        g_cursor[gi] = c;
        g_cur2[gi]   = c;
    }
    if (gi == 0) g_cursor[2*NN] = 2*EE;
}

__global__ void scatter_kernel(const int* __restrict__ ei) {
    int i = blockIdx.x*blockDim.x + threadIdx.x;
    if (i >= 2*EE) return;
    int t = i >= EE;
    int e = i - t*EE;
    int src = ei[(size_t)t*2*EE + e];
    int dst = ei[(size_t)t*2*EE + EE + e];
    int pos = atomicAdd(&g_cur2[(1-t)*NN + dst], 1);
    g_srt[pos] = (uint32_t)src;
}

// split float4 -> two fp16x2 hi words + two fp16x2 lo (residual) words
__device__ __forceinline__ void split4h(float4 v, uint32_t* hi2, uint32_t* lo2) {
    __half2 h01 = __floats2half2_rn(v.x, v.y);
    __half2 h23 = __floats2half2_rn(v.z, v.w);
    __half2 l01 = __floats2half2_rn(v.x - __half2float(__low2half(h01)),
                                    v.y - __half2float(__high2half(h01)));
    __half2 l23 = __floats2half2_rn(v.z - __half2float(__low2half(h23)),
                                    v.w - __half2float(__high2half(h23)));
    hi2[0] = *reinterpret_cast<uint32_t*>(&h01);
    hi2[1] = *reinterpret_cast<uint32_t*>(&h23);
    lo2[0] = *reinterpret_cast<uint32_t*>(&l01);
    lo2[1] = *reinterpret_cast<uint32_t*>(&l23);
}

// copy one packed fp16 weight matrix (32KB) into the padded B buffer at b_off
__device__ __forceinline__ void copy_B(char* sm, uint32_t b_off, int mat, int nt, int tid) {
    const uint4* src = (const uint4*)(g_Wh + (size_t)(mat*2 + nt) * 16384);
    #pragma unroll 2
    for (int i = tid; i < 2048; i += 256) {
        int row = i >> 4, chunk = i & 15;
        *(uint4*)(sm + b_off + row*ROWB + chunk*16) = src[i];
    }
}

// 1-term fp16 GEMM: acc += Ah*B
__device__ __forceinline__ void gemm_1term(uint32_t su, int w, int lane, float acc[2][8][4]) {
    int wm = w & 3, wn = w >> 2;
    int mat = lane >> 3, r8 = lane & 7;
    uint32_t aoff = (uint32_t)(wm*32 + (mat&1)*8 + r8)*ROWB + (mat>>1)*16;
    uint32_t boff = (uint32_t)(wn*64 + (mat>>1)*8 + r8)*ROWB + (mat&1)*16 + PROJ_B_OFF;

    #pragma unroll
    for (int kk = 0; kk < 8; kk++) {
        uint32_t kb = kk*32;
        uint32_t A[2][4], B[8][2];
        #pragma unroll
        for (int mt = 0; mt < 2; mt++) {
            uint32_t ao = aoff + mt*16*ROWB + kb;
            LDSM4(A[mt][0], A[mt][1], A[mt][2], A[mt][3], su + A_HI_OFF + ao);
        }
        #pragma unroll
        for (int p = 0; p < 4; p++) {
            uint32_t bo = boff + p*16*ROWB + kb;
            LDSM4(B[2*p][0], B[2*p][1], B[2*p+1][0], B[2*p+1][1], su + bo);
        }
        #pragma unroll
        for (int mt = 0; mt < 2; mt++)
            #pragma unroll
            for (int nt = 0; nt < 8; nt++)
                MMA16816F16(acc[mt][nt], A[mt][0],A[mt][1],A[mt][2],A[mt][3], B[nt][0],B[nt][1]);
    }
}

// 2-term fp16 GEMM: acc += Ah*B + Al*B  (A = Ah+Al exact, B single-rounded fp16)
__device__ __forceinline__ void gemm_2term(uint32_t su, int w, int lane, float acc[2][8][4]) {
    int wm = w & 3, wn = w >> 2;
    int mat = lane >> 3, r8 = lane & 7;
    uint32_t aoff = (uint32_t)(wm*32 + (mat&1)*8 + r8)*ROWB + (mat>>1)*16;
    uint32_t boff = (uint32_t)(wn*64 + (mat>>1)*8 + r8)*ROWB + (mat&1)*16 + NODE_B_OFF;

    #pragma unroll
    for (int kk = 0; kk < 8; kk++) {
        uint32_t kb = kk*32;
        uint32_t Ah[2][4], Al[2][4], B[8][2];
        #pragma unroll
        for (int mt = 0; mt < 2; mt++) {
            uint32_t ao = aoff + mt*16*ROWB + kb;
            LDSM4(Ah[mt][0], Ah[mt][1], Ah[mt][2], Ah[mt][3], su + A_HI_OFF + ao);
            LDSM4(Al[mt][0], Al[mt][1], Al[mt][2], Al[mt][3], su + A_LO_OFF + ao);
        }
        #pragma unroll
        for (int p = 0; p < 4; p++) {
            uint32_t bo = boff + p*16*ROWB + kb;
            LDSM4(B[2*p][0], B[2*p][1], B[2*p+1][0], B[2*p+1][1], su + bo);
        }
        #pragma unroll
        for (int mt = 0; mt < 2; mt++)
            #pragma unroll
            for (int nt = 0; nt < 8; nt++) {
                MMA16816F16(acc[mt][nt], Ah[mt][0],Ah[mt][1],Ah[mt][2],Ah[mt][3], B[nt][0],B[nt][1]);
                MMA16816F16(acc[mt][nt], Al[mt][0],Al[mt][1],Al[mt][2],Al[mt][3], B[nt][0],B[nt][1]);
            }
    }
}

// ---------------- proj: Ktr, Mtr, Q via 1-term mma.sync -> fp16 tables ----------------
__global__ void __launch_bounds__(256, 2) proj_mma_kernel(const float* __restrict__ x,
                                                          const float* __restrict__ bq) {
    extern __shared__ char sm[];
    uint32_t su = smem_u32(sm);
    int tid = threadIdx.x;
    int w = tid >> 5, lane = tid & 31;
    int wm = w & 3, wn = w >> 2;

    int blk = blockIdx.x;
    int ntp = blk >= TILES;
    int tb  = blk - ntp*TILES;
    int base = tb*128; if (base > NN-128) base = NN-128;
    size_t nbase = (size_t)ntp*NN + base;

    // stage A: x rows -> fp16 smem (single-rounded)
    #pragma unroll 4
    for (int j = 0; j < 16; j++) {
        int idx = tid + j*256;             // 4096 float4
        int row = idx >> 5, c4 = idx & 31;
        float4 v = ((const float4*)(x + (nbase + row)*INF))[c4];
        __half2 h01 = __floats2half2_rn(v.x, v.y);
        __half2 h23 = __floats2half2_rn(v.z, v.w);
        *(uint32_t*)(sm + A_HI_OFF + row*ROWB + c4*8)     = *reinterpret_cast<uint32_t*>(&h01);
        *(uint32_t*)(sm + A_HI_OFF + row*ROWB + c4*8 + 4) = *reinterpret_cast<uint32_t*>(&h23);
    }

    for (int m = 0; m < 3; m++) {
        __syncthreads();
        copy_B(sm, PROJ_B_OFF, m, ntp, tid);
        __syncthreads();

        const float* bias = (m==0) ? g_bkA + ntp*OUTF
                          : (m==1) ? g_bmM + ntp*OUTF
                                   : bq    + ntp*OUTF;
        float acc[2][8][4];
        #pragma unroll
        for (int mt = 0; mt < 2; mt++)
            #pragma unroll
            for (int nt = 0; nt < 8; nt++) {
                int col = wn*64 + nt*8 + 2*(lane & 3);
                float b0 = bias[col], b1 = bias[col+1];
                acc[mt][nt][0] = b0; acc[mt][nt][1] = b1;
                acc[mt][nt][2] = b0; acc[mt][nt][3] = b1;
            }
        gemm_1term(su, w, lane, acc);
        __syncthreads();   // all warps done with B before staging reuses it

        // stage fp16 result into B buffer: 128 rows x 256B (+ ROWB pad)
        __half* H = (__half*)(sm + PROJ_B_OFF);
        #pragma unroll
        for (int mt = 0; mt < 2; mt++)
            #pragma unroll
            for (int nt = 0; nt < 8; nt++) {
                int row = wm*32 + mt*16 + (lane >> 2);
                int col = wn*64 + nt*8 + 2*(lane & 3);
                *(__half2*)((char*)H + row*ROWB + col*2) =
                    __floats2half2_rn(acc[mt][nt][0], acc[mt][nt][1]);
                *(__half2*)((char*)H + (row+8)*ROWB + col*2) =
                    __floats2half2_rn(acc[mt][nt][2], acc[mt][nt][3]);
            }
        __syncthreads();

        // coalesced copy-out: 128 rows x 256B
        #pragma unroll
        for (int i = tid; i < 2048; i += 256) {
            int row = i >> 4, ch = i & 15;
            uint4 v = *(uint4*)((char*)H + row*ROWB + ch*16);
            __half* dst = (m == 2) ? g_Qh + (nbase + row)*OUTF + ch*8
                                   : g_KMh + ((nbase + row)*2 + m)*OUTF + ch*8;
            *(uint4*)dst = v;
        }
    }
}

// ---------------- edge pass: one warp per dst node, 2 edges/iter, 2-pair pipeline ----
__global__ void __launch_bounds__(256) edge_node_kernel() {
    int wid  = (blockIdx.x*blockDim.x + threadIdx.x) >> 5;   // node id [0, 2N)
    int lane = threadIdx.x & 31;
    if (wid >= 2*NN) return;
    int d = wid >= NN;
    int s = 1 - d;

    int start = g_cursor[wid];
    int end   = g_cursor[wid + 1];

    if (start == end) {   // empty segment: zeros
        ((float4*)(g_agg + (size_t)wid*OUTF))[lane] = make_float4(0.f,0.f,0.f,0.f);
        if ((lane & 7) == 0) g_den[(size_t)wid*HH + (lane >> 3)] = 0.f;
        return;
    }

    uint2 qv = ((const uint2*)(g_Qh + (size_t)wid*OUTF))[lane];
    float2 qa = __half22float2(*(const __half2*)&qv.x);
    float2 qb = __half22float2(*(const __half2*)&qv.y);

    float4 acc = make_float4(0.f, 0.f, 0.f, 0.f);
    float den = 0.f;

    const __half* KMbase = g_KMh + (size_t)s*NN*2*OUTF;

    // current pair in flight
    uint2 kc0, mc0, kc1, mc1;
    {
        int sc0 = (int)g_srt[start];
        const uint2* km0 = (const uint2*)(KMbase + (size_t)sc0*2*OUTF);
        kc0 = km0[lane]; mc0 = km0[32 + lane];
        if (start + 1 < end) {
            int sc1 = (int)g_srt[start + 1];
            const uint2* km1 = (const uint2*)(KMbase + (size_t)sc1*2*OUTF);
            kc1 = km1[lane]; mc1 = km1[32 + lane];
        }
    }

    for (int i = start; i < end; i += 2) {
        uint2 k0 = kc0, m0 = mc0, k1 = kc1, m1 = mc1;
        bool has1 = (i + 1 < end);
        // prefetch next pair
        if (i + 2 < end) {
            int sc0 = (int)g_srt[i + 2];
            const uint2* km0 = (const uint2*)(KMbase + (size_t)sc0*2*OUTF);
            kc0 = km0[lane]; mc0 = km0[32 + lane];
            if (i + 3 < end) {
                int sc1 = (int)g_srt[i + 3];
                const uint2* km1 = (const uint2*)(KMbase + (size_t)sc1*2*OUTF);
                kc1 = km1[lane]; mc1 = km1[32 + lane];
            }
        }

        // edge i
        {
            float2 ka = __half22float2(*(const __half2*)&k0.x);
            float2 kb = __half22float2(*(const __half2*)&k0.y);
            float p = ka.x*qa.x + ka.y*qa.y + kb.x*qb.x + kb.y*qb.y;
            p += __shfl_down_sync(0xffffffffu, p, 4, 8);
            p += __shfl_down_sync(0xffffffffu, p, 2, 8);
            p += __shfl_down_sync(0xffffffffu, p, 1, 8);
            float att = __shfl_sync(0xffffffffu, p, 0, 8);
            float ev  = __expf(att);
            float2 ma = __half22float2(*(const __half2*)&m0.x);
            float2 mb = __half22float2(*(const __half2*)&m0.y);
            acc.x += ma.x*ev; acc.y += ma.y*ev;
            acc.z += mb.x*ev; acc.w += mb.y*ev;
            den += ev;
        }
        // edge i+1
        if (has1) {
            float2 ka = __half22float2(*(const __half2*)&k1.x);
            float2 kb = __half22float2(*(const __half2*)&k1.y);
            float p = ka.x*qa.x + ka.y*qa.y + kb.x*qb.x + kb.y*qb.y;
            p += __shfl_down_sync(0xffffffffu, p, 4, 8);
            p += __shfl_down_sync(0xffffffffu, p, 2, 8);
            p += __shfl_down_sync(0xffffffffu, p, 1, 8);
            float att = __shfl_sync(0xffffffffu, p, 0, 8);
            float ev  = __expf(att);
            float2 ma = __half22float2(*(const __half2*)&m1.x);
            float2 mb = __half22float2(*(const __half2*)&m1.y);
            acc.x += ma.x*ev; acc.y += ma.y*ev;
            acc.z += mb.x*ev; acc.w += mb.y*ev;
            den += ev;
        }
    }

    ((float4*)(g_agg + (size_t)wid*OUTF))[lane] = acc;
    if ((lane & 7) == 0)
        g_den[(size_t)wid*HH + (lane >> 3)] = den;
}

// ---------------- node pass: gelu(agg/den) -> 2-term mma GEMM -> skip + LN ------
__global__ void __launch_bounds__(256, 2) node_mma_kernel(const float* __restrict__ x,
                                                          const float* __restrict__ ba,
                                                          const float* __restrict__ skip,
                                                          const float* __restrict__ lns,
                                                          const float* __restrict__ lnb,
                                                          float* __restrict__ out) {
    extern __shared__ char sm[];
    uint32_t su = smem_u32(sm);
    float* S = (float*)sm;        // reuse A hi/lo region after GEMM: [128][136] f32
    int tid = threadIdx.x;
    int w = tid >> 5, lane = tid & 31;
    int wm = w & 3, wn = w >> 2;

    int blk = blockIdx.x;
    int ntp = blk >= TILES;
    int tb  = blk - ntp*TILES;
    int base = tb*128; if (base > NN-128) base = NN-128;
    size_t nbase = (size_t)ntp*NN + base;

    // stage A = gelu(agg/den) -> fp16 hi/lo smem
    #pragma unroll 4
    for (int j = 0; j < 16; j++) {
        int idx = tid + j*256;
        int row = idx >> 5, c4 = idx & 31;
        size_t nrow = nbase + row;
        float4 v = ((const float4*)(g_agg + nrow*OUTF))[c4];
        float idn = 1.f / (g_den[nrow*HH + (c4 >> 3)] + 1e-16f);
        v.x *= idn; v.y *= idn; v.z *= idn; v.w *= idn;
        v.x = 0.5f*v.x*(1.f + erff(v.x*0.70710678118654752f));
        v.y = 0.5f*v.y*(1.f + erff(v.y*0.70710678118654752f));
        v.z = 0.5f*v.z*(1.f + erff(v.z*0.70710678118654752f));
        v.w = 0.5f*v.w*(1.f + erff(v.w*0.70710678118654752f));
        uint32_t hi[2], lo[2];
        split4h(v, hi, lo);
        *(uint32_t*)(sm + A_HI_OFF + row*ROWB + c4*8)     = hi[0];
        *(uint32_t*)(sm + A_HI_OFF + row*ROWB + c4*8 + 4) = hi[1];
        *(uint32_t*)(sm + A_LO_OFF + row*ROWB + c4*8)     = lo[0];
        *(uint32_t*)(sm + A_LO_OFF + row*ROWB + c4*8 + 4) = lo[1];
    }
    __syncthreads();
    copy_B(sm, NODE_B_OFF, 3, ntp, tid);
    __syncthreads();

    float acc[2][8][4];
    #pragma unroll
    for (int mt = 0; mt < 2; mt++)
        #pragma unroll
        for (int nt = 0; nt < 8; nt++) {
            int col = wn*64 + nt*8 + 2*(lane & 3);
            float b0 = ba[ntp*OUTF + col], b1 = ba[ntp*OUTF + col + 1];
            acc[mt][nt][0] = b0; acc[mt][nt][1] = b1;
            acc[mt][nt][2] = b0; acc[mt][nt][3] = b1;
        }
    gemm_2term(su, w, lane, acc);
    __syncthreads();   // all warps done reading A region before reuse as S

    // acc -> S [128][136] f32
    #pragma unroll
    for (int mt = 0; mt < 2; mt++)
        #pragma unroll
        for (int nt = 0; nt < 8; nt++) {
            int row = wm*32 + mt*16 + (lane >> 2);
            int col = wn*64 + nt*8 + 2*(lane & 3);
            *(float2*)(S + row*136 + col)     = make_float2(acc[mt][nt][0], acc[mt][nt][1]);
            *(float2*)(S + (row+8)*136 + col) = make_float2(acc[mt][nt][2], acc[mt][nt][3]);
        }
    __syncthreads();

    // skip blend
    float alpha = 1.f / (1.f + __expf(-skip[ntp]));
    float beta  = 1.f - alpha;
    #pragma unroll 4
    for (int i = tid; i < 128*128; i += 256) {
        int r = i >> 7, c = i & 127;
        S[r*136 + c] = alpha*S[r*136 + c] + beta*x[(nbase + r)*INF + c];
    }
    __syncthreads();

    // layernorm: warp w rows 16w..16w+15
    for (int rr = 0; rr < 16; rr++) {
        int r = w*16 + rr;
        float s1 = 0.f, s2 = 0.f;
        #pragma unroll
        for (int c = lane; c < OUTF; c += 32) { float v = S[r*136 + c]; s1 += v; s2 += v*v; }
        #pragma unroll
        for (int off = 16; off; off >>= 1) {
            s1 += __shfl_xor_sync(0xffffffffu, s1, off);
            s2 += __shfl_xor_sync(0xffffffffu, s2, off);
        }
        float mean = s1 * (1.f/OUTF);
        float var  = s2 * (1.f/OUTF) - mean*mean;
        float inv  = rsqrtf(var + 1e-5f);
        #pragma unroll
        for (int c = lane; c < OUTF; c += 32)
            out[(nbase + r)*OUTF + c] = (S[r*136 + c] - mean)*inv*lns[ntp*OUTF + c]
                                        + lnb[ntp*OUTF + c];
    }
}

// ---------------- launch ----------------
extern "C" void kernel_launch(void* const* d_in, const int* in_sizes, int n_in,
                              void* d_out, int out_size) {
    const float* x     = (const float*)d_in[0];
    const int*   ei    = (const int*)  d_in[1];
    const float* Wk    = (const float*)d_in[2];
    const float* bk    = (const float*)d_in[3];
    const float* Wq    = (const float*)d_in[4];
    const float* bq    = (const float*)d_in[5];
    const float* Wm    = (const float*)d_in[6];
    const float* bm    = (const float*)d_in[7];
    const float* Wa    = (const float*)d_in[8];
    const float* ba    = (const float*)d_in[9];
    const float* w_att = (const float*)d_in[10];
    const float* w_msg = (const float*)d_in[11];
    const float* mu    = (const float*)d_in[12];
    const float* skip  = (const float*)d_in[13];
    const float* lns   = (const float*)d_in[14];
    const float* lnb   = (const float*)d_in[15];
    float* out = (float*)d_out;

    cudaFuncSetAttribute(proj_mma_kernel, cudaFuncAttributeMaxDynamicSharedMemorySize, SMEM_PROJ);
    cudaFuncSetAttribute(node_mma_kernel, cudaFuncAttributeMaxDynamicSharedMemorySize, SMEM_NODE);

    prep_fold<<<256, 256>>>(Wk, bk, Wm, bm, w_att, w_msg, mu);
    prep_pack<<<512, 256>>>(Wq, Wa);
    zero_hist<<<(2*NN + 255)/256, 256>>>();
    hist_kernel<<<(2*EE + 255)/256, 256>>>(ei);
    scan_blocks<<<(2*NN + 1023)/1024, 1024>>>();
    scan_tops<<<1, 512>>>();
    add_offs<<<(2*NN + 1023)/1024, 1024>>>();
    scatter_kernel<<<(2*EE + 255)/256, 256>>>(ei);
    proj_mma_kernel<<<2*TILES, 256, SMEM_PROJ>>>(x, bq);
    edge_node_kernel<<<(2*NN*32 + 255)/256, 256>>>();
    node_mma_kernel<<<2*TILES, 256, SMEM_NODE>>>(x, ba, skip, lns, lnb, out);
}

// round 13
// speedup vs baseline: 1.1903x; 1.0364x over previous
#include <cuda_runtime.h>
#include <cuda_fp16.h>
#include <math.h>
#include <stdint.h>

#define NN 200000
#define EE 1000000
#define INF 128
#define OUTF 128
#define HH 4
#define DKK 32
#define TILES 1563            // ceil(NN/128)

// smem layout (bytes): rows padded to 272B (conflict-free LDSM)
#define ROWB 272
#define A_HI_OFF 0
#define B_OFF    34816        // B right after A_HI (1-term GEMMs everywhere)
#define SMEM_TOT 69632

// ---------------- scratch (device globals; no allocation) ----------------
__device__ __half g_KMh[(size_t)2*NN*2*OUTF];   // K/M interleaved fp16: [2N][2][128]
__device__ __half g_Qh [(size_t)2*NN*OUTF];     // fp16
__device__ float  g_agg[(size_t)2*NN*OUTF];
__device__ float  g_den[(size_t)2*NN*HH];
__device__ float  g_WkA[2*INF*OUTF];
__device__ float  g_bkA[2*OUTF];
__device__ float  g_WmM[2*INF*OUTF];
__device__ float  g_bmM[2*OUTF];
// packed fp16 weights, W^T layout [o][k]: [mat(4)][type(2)][128*128]
__device__ __half g_Wh[(size_t)4*2*16384];
// exact-dst sorted edges: srcs only, grouped by destination node (d-major)
__device__ uint32_t g_srt[(size_t)2*EE];
__device__ int    g_hist[2*NN];
__device__ int    g_cursor[2*NN + 1];
__device__ int    g_cur2[2*NN];
__device__ int    g_bsum[512];
__device__ int    g_bsumx[512];

#define MMA16816F16(acc, A0,A1,A2,A3, B0,B1) \
  asm volatile("mma.sync.aligned.m16n8k16.row.col.f32.f16.f16.f32 " \
    "{%0,%1,%2,%3}, {%4,%5,%6,%7}, {%8,%9}, {%0,%1,%2,%3};" \
    : "+f"((acc)[0]), "+f"((acc)[1]), "+f"((acc)[2]), "+f"((acc)[3]) \
    : "r"(A0), "r"(A1), "r"(A2), "r"(A3), "r"(B0), "r"(B1))

#define LDSM4(r0,r1,r2,r3,addr) \
  asm volatile("ldmatrix.sync.aligned.m8n8.x4.shared.b16 {%0,%1,%2,%3}, [%4];" \
    : "=r"(r0), "=r"(r1), "=r"(r2), "=r"(r3) : "r"(addr))

__device__ __forceinline__ uint32_t smem_u32(const void* p) {
    uint32_t a;
    asm("{ .reg .u64 t; cvta.to.shared.u64 t, %1; cvt.u32.u64 %0, t; }" : "=r"(a) : "l"(p));
    return a;
}

// ---------------- prep: fold w_att/w_msg (+ mu*scale) into projection weights
__global__ void prep_fold(const float* __restrict__ Wk, const float* __restrict__ bk,
                          const float* __restrict__ Wm, const float* __restrict__ bm,
                          const float* __restrict__ w_att, const float* __restrict__ w_msg,
                          const float* __restrict__ mu) {
    int idx = blockIdx.x*blockDim.x + threadIdx.x;     // 65536
    const int total = 2*INF*OUTF;
    int m   = idx / total;
    int rem = idx - m*total;
    int t   = rem / (INF*OUTF);
    int io  = rem - t*(INF*OUTF);
    int i   = io / OUTF;
    int o   = io - i*OUTF;
    int h   = o >> 5, f = o & 31;

    const float* W = m ? Wm : Wk;
    const float* R = m ? w_msg : w_att;
    const float* wrow = W + ((size_t)t*INF + i)*OUTF + h*DKK;
    const float* rr   = R + (((size_t)t*HH + h)*DKK)*DKK + f;
    float s = 0.f;
    #pragma unroll
    for (int d = 0; d < DKK; d++) s += wrow[d] * rr[(size_t)d*DKK];
    float fold = m ? 1.f : mu[t*HH + h] * 0.17677669529663687f;   // mu / sqrt(DK)
    (m ? g_WmM : g_WkA)[(size_t)t*INF*OUTF + io] = s * fold;

    if (i == 0) {
        const float* b = m ? bm : bk;
        float sb = 0.f;
        #pragma unroll
        for (int d = 0; d < DKK; d++) sb += b[t*OUTF + h*DKK + d] * rr[(size_t)d*DKK];
        (m ? g_bmM : g_bkA)[t*OUTF + o] = sb * fold;
    }
}

// pack 4 matrices (Kfold, Mfold, Q, A) per type as W^T [o][k] fp16
__global__ void prep_pack(const float* __restrict__ Wq, const float* __restrict__ Wa) {
    int idx = blockIdx.x*blockDim.x + threadIdx.x;   // 131072
    int mat = idx >> 15;
    int rem = idx & 32767;
    int t   = rem >> 14;
    int ok  = rem & 16383;
    int o   = ok >> 7;
    int k   = ok & 127;
    const float* W = (mat==0) ? g_WkA : (mat==1) ? g_WmM : (mat==2) ? Wq : Wa;
    float v = W[((size_t)t*INF + k)*OUTF + o];
    g_Wh[(size_t)(mat*2 + t)*16384 + ok] = __float2half(v);
}

// ---------------- zero per-dst histogram ----------------
__global__ void zero_hist() {
    int i = blockIdx.x*blockDim.x + threadIdx.x;
    if (i < 2*NN) g_hist[i] = 0;
}

// ---------------- exact-dst bucketing: histogram -> 2-level scan -> scatter ----
__global__ void hist_kernel(const int* __restrict__ ei) {
    int i = blockIdx.x*blockDim.x + threadIdx.x;
    if (i >= 2*EE) return;
    int t = i >= EE;
    int e = i - t*EE;
    int dst = ei[(size_t)t*2*EE + EE + e];
    atomicAdd(&g_hist[(1-t)*NN + dst], 1);     // node key = d*NN + dst
}

__global__ void scan_blocks() {                // 391 blocks x 1024
    __shared__ int ss[1024];
    int tid = threadIdx.x;
    int gi = blockIdx.x*1024 + tid;
    int v = (gi < 2*NN) ? g_hist[gi] : 0;
    ss[tid] = v;
    __syncthreads();
    for (int off = 1; off < 1024; off <<= 1) {
        int u = (tid >= off) ? ss[tid-off] : 0;
        __syncthreads();
        ss[tid] += u;
        __syncthreads();
    }
    if (gi < 2*NN) g_cursor[gi] = ss[tid] - v;   // exclusive within block
    if (tid == 1023) g_bsum[blockIdx.x] = ss[1023];
}

__global__ void scan_tops() {                  // 1 block x 512 (covers 391 block sums)
    __shared__ int ss[512];
    int tid = threadIdx.x;
    int v = (tid < 391) ? g_bsum[tid] : 0;
    ss[tid] = v;
    __syncthreads();
    for (int off = 1; off < 512; off <<= 1) {
        int u = (tid >= off) ? ss[tid-off] : 0;
        __syncthreads();
        ss[tid] += u;
        __syncthreads();
    }
    g_bsumx[tid] = ss[tid] - v;                // exclusive
}

__global__ void add_offs() {                   // 391 blocks x 1024
    int tid = threadIdx.x;
    int gi = blockIdx.x*1024 + tid;
    if (gi < 2*NN) {
        int c = g_cursor[gi] + g_bsumx[blockIdx.x];
        g_cursor[gi] = c;
        g_cur2[gi]   = c;
    }
    if (gi == 0) g_cursor[2*NN] = 2*EE;
}

__global__ void scatter_kernel(const int* __restrict__ ei) {
    int i = blockIdx.x*blockDim.x + threadIdx.x;
    if (i >= 2*EE) return;
    int t = i >= EE;
    int e = i - t*EE;
    int src = ei[(size_t)t*2*EE + e];
    int dst = ei[(size_t)t*2*EE + EE + e];
    int pos = atomicAdd(&g_cur2[(1-t)*NN + dst], 1);
    g_srt[pos] = (uint32_t)src;
}

// copy one packed fp16 weight matrix (32KB) into the padded B buffer
__device__ __forceinline__ void copy_B(char* sm, int mat, int nt, int tid) {
    const uint4* src = (const uint4*)(g_Wh + (size_t)(mat*2 + nt) * 16384);
    #pragma unroll 2
    for (int i = tid; i < 2048; i += 256) {
        int row = i >> 4, chunk = i & 15;
        *(uint4*)(sm + B_OFF + row*ROWB + chunk*16) = src[i];
    }
}

// 1-term fp16 GEMM: acc += A*B
__device__ __forceinline__ void gemm_1term(uint32_t su, int w, int lane, float acc[2][8][4]) {
    int wm = w & 3, wn = w >> 2;
    int mat = lane >> 3, r8 = lane & 7;
    uint32_t aoff = (uint32_t)(wm*32 + (mat&1)*8 + r8)*ROWB + (mat>>1)*16;
    uint32_t boff = (uint32_t)(wn*64 + (mat>>1)*8 + r8)*ROWB + (mat&1)*16 + B_OFF;

    #pragma unroll
    for (int kk = 0; kk < 8; kk++) {
        uint32_t kb = kk*32;
        uint32_t A[2][4], B[8][2];
        #pragma unroll
        for (int mt = 0; mt < 2; mt++) {
            uint32_t ao = aoff + mt*16*ROWB + kb;
            LDSM4(A[mt][0], A[mt][1], A[mt][2], A[mt][3], su + A_HI_OFF + ao);
        }
        #pragma unroll
        for (int p = 0; p < 4; p++) {
            uint32_t bo = boff + p*16*ROWB + kb;
            LDSM4(B[2*p][0], B[2*p][1], B[2*p+1][0], B[2*p+1][1], su + bo);
        }
        #pragma unroll
        for (int mt = 0; mt < 2; mt++)
            #pragma unroll
            for (int nt = 0; nt < 8; nt++)
                MMA16816F16(acc[mt][nt], A[mt][0],A[mt][1],A[mt][2],A[mt][3], B[nt][0],B[nt][1]);
    }
}

// ---------------- proj: Ktr, Mtr, Q via 1-term mma.sync -> fp16 tables ----------------
__global__ void __launch_bounds__(256, 2) proj_mma_kernel(const float* __restrict__ x,
                                                          const float* __restrict__ bq) {
    extern __shared__ char sm[];
    uint32_t su = smem_u32(sm);
    int tid = threadIdx.x;
    int w = tid >> 5, lane = tid & 31;
    int wm = w & 3, wn = w >> 2;

    int blk = blockIdx.x;
    int ntp = blk >= TILES;
    int tb  = blk - ntp*TILES;
    int base = tb*128; if (base > NN-128) base = NN-128;
    size_t nbase = (size_t)ntp*NN + base;

    // stage A: x rows -> fp16 smem (single-rounded)
    #pragma unroll 4
    for (int j = 0; j < 16; j++) {
        int idx = tid + j*256;             // 4096 float4
        int row = idx >> 5, c4 = idx & 31;
        float4 v = ((const float4*)(x + (nbase + row)*INF))[c4];
        __half2 h01 = __floats2half2_rn(v.x, v.y);
        __half2 h23 = __floats2half2_rn(v.z, v.w);
        *(uint32_t*)(sm + A_HI_OFF + row*ROWB + c4*8)     = *reinterpret_cast<uint32_t*>(&h01);
        *(uint32_t*)(sm + A_HI_OFF + row*ROWB + c4*8 + 4) = *reinterpret_cast<uint32_t*>(&h23);
    }

    for (int m = 0; m < 3; m++) {
        __syncthreads();
        copy_B(sm, m, ntp, tid);
        __syncthreads();

        const float* bias = (m==0) ? g_bkA + ntp*OUTF
                          : (m==1) ? g_bmM + ntp*OUTF
                                   : bq    + ntp*OUTF;
        float acc[2][8][4];
        #pragma unroll
        for (int mt = 0; mt < 2; mt++)
            #pragma unroll
            for (int nt = 0; nt < 8; nt++) {
                int col = wn*64 + nt*8 + 2*(lane & 3);
                float b0 = bias[col], b1 = bias[col+1];
                acc[mt][nt][0] = b0; acc[mt][nt][1] = b1;
                acc[mt][nt][2] = b0; acc[mt][nt][3] = b1;
            }
        gemm_1term(su, w, lane, acc);
        __syncthreads();   // all warps done with B before staging reuses it

        // stage fp16 result into B buffer: 128 rows x 256B (+ ROWB pad)
        __half* H = (__half*)(sm + B_OFF);
        #pragma unroll
        for (int mt = 0; mt < 2; mt++)
            #pragma unroll
            for (int nt = 0; nt < 8; nt++) {
                int row = wm*32 + mt*16 + (lane >> 2);
                int col = wn*64 + nt*8 + 2*(lane & 3);
                *(__half2*)((char*)H + row*ROWB + col*2) =
                    __floats2half2_rn(acc[mt][nt][0], acc[mt][nt][1]);
                *(__half2*)((char*)H + (row+8)*ROWB + col*2) =
                    __floats2half2_rn(acc[mt][nt][2], acc[mt][nt][3]);
            }
        __syncthreads();

        // coalesced copy-out: 128 rows x 256B
        #pragma unroll
        for (int i = tid; i < 2048; i += 256) {
            int row = i >> 4, ch = i & 15;
            uint4 v = *(uint4*)((char*)H + row*ROWB + ch*16);
            __half* dst = (m == 2) ? g_Qh + (nbase + row)*OUTF + ch*8
                                   : g_KMh + ((nbase + row)*2 + m)*OUTF + ch*8;
            *(uint4*)dst = v;
        }
    }
}

// ---------------- edge pass: one warp per dst node, 2 edges/iter, 2-pair pipeline ----
__global__ void __launch_bounds__(256) edge_node_kernel() {
    int wid  = (blockIdx.x*blockDim.x + threadIdx.x) >> 5;   // node id [0, 2N)
    int lane = threadIdx.x & 31;
    if (wid >= 2*NN) return;
    int d = wid >= NN;
    int s = 1 - d;

    int start = g_cursor[wid];
    int end   = g_cursor[wid + 1];

    if (start == end) {   // empty segment: zeros
        ((float4*)(g_agg + (size_t)wid*OUTF))[lane] = make_float4(0.f,0.f,0.f,0.f);
        if ((lane & 7) == 0) g_den[(size_t)wid*HH + (lane >> 3)] = 0.f;
        return;
    }

    uint2 qv = ((const uint2*)(g_Qh + (size_t)wid*OUTF))[lane];
    float2 qa = __half22float2(*(const __half2*)&qv.x);
    float2 qb = __half22float2(*(const __half2*)&qv.y);

    float4 acc = make_float4(0.f, 0.f, 0.f, 0.f);
    float den = 0.f;

    const __half* KMbase = g_KMh + (size_t)s*NN*2*OUTF;

    // current pair in flight
    uint2 kc0, mc0, kc1, mc1;
    {
        int sc0 = (int)g_srt[start];
        const uint2* km0 = (const uint2*)(KMbase + (size_t)sc0*2*OUTF);
        kc0 = km0[lane]; mc0 = km0[32 + lane];
        if (start + 1 < end) {
            int sc1 = (int)g_srt[start + 1];
            const uint2* km1 = (const uint2*)(KMbase + (size_t)sc1*2*OUTF);
            kc1 = km1[lane]; mc1 = km1[32 + lane];
        }
    }

    for (int i = start; i < end; i += 2) {
        uint2 k0 = kc0, m0 = mc0, k1 = kc1, m1 = mc1;
        bool has1 = (i + 1 < end);
        // prefetch next pair
        if (i + 2 < end) {
            int sc0 = (int)g_srt[i + 2];
            const uint2* km0 = (const uint2*)(KMbase + (size_t)sc0*2*OUTF);
            kc0 = km0[lane]; mc0 = km0[32 + lane];
            if (i + 3 < end) {
                int sc1 = (int)g_srt[i + 3];
                const uint2* km1 = (const uint2*)(KMbase + (size_t)sc1*2*OUTF);
                kc1 = km1[lane]; mc1 = km1[32 + lane];
            }
        }

        // edge i
        {
            float2 ka = __half22float2(*(const __half2*)&k0.x);
            float2 kb = __half22float2(*(const __half2*)&k0.y);
            float p = ka.x*qa.x + ka.y*qa.y + kb.x*qb.x + kb.y*qb.y;
            p += __shfl_down_sync(0xffffffffu, p, 4, 8);
            p += __shfl_down_sync(0xffffffffu, p, 2, 8);
            p += __shfl_down_sync(0xffffffffu, p, 1, 8);
            float att = __shfl_sync(0xffffffffu, p, 0, 8);
            float ev  = __expf(att);
            float2 ma = __half22float2(*(const __half2*)&m0.x);
            float2 mb = __half22float2(*(const __half2*)&m0.y);
            acc.x += ma.x*ev; acc.y += ma.y*ev;
            acc.z += mb.x*ev; acc.w += mb.y*ev;
            den += ev;
        }
        // edge i+1
        if (has1) {
            float2 ka = __half22float2(*(const __half2*)&k1.x);
            float2 kb = __half22float2(*(const __half2*)&k1.y);
            float p = ka.x*qa.x + ka.y*qa.y + kb.x*qb.x + kb.y*qb.y;
            p += __shfl_down_sync(0xffffffffu, p, 4, 8);
            p += __shfl_down_sync(0xffffffffu, p, 2, 8);
            p += __shfl_down_sync(0xffffffffu, p, 1, 8);
            float att = __shfl_sync(0xffffffffu, p, 0, 8);
            float ev  = __expf(att);
            float2 ma = __half22float2(*(const __half2*)&m1.x);
            float2 mb = __half22float2(*(const __half2*)&m1.y);
            acc.x += ma.x*ev; acc.y += ma.y*ev;
            acc.z += mb.x*ev; acc.w += mb.y*ev;
            den += ev;
        }
    }

    ((float4*)(g_agg + (size_t)wid*OUTF))[lane] = acc;
    if ((lane & 7) == 0)
        g_den[(size_t)wid*HH + (lane >> 3)] = den;
}

// ---------------- node pass: gelu(agg/den) -> 1-term mma GEMM -> skip + LN ------
__global__ void __launch_bounds__(256, 2) node_mma_kernel(const float* __restrict__ x,
                                                          const float* __restrict__ ba,
                                                          const float* __restrict__ skip,
                                                          const float* __restrict__ lns,
                                                          const float* __restrict__ lnb,
                                                          float* __restrict__ out) {
    extern __shared__ char sm[];
    uint32_t su = smem_u32(sm);
    float* S = (float*)sm;        // reuse A region after GEMM: [128][136] f32 = 69632B... fits in 68KB? 128*136*4 = 69632 exactly
    int tid = threadIdx.x;
    int w = tid >> 5, lane = tid & 31;
    int wm = w & 3, wn = w >> 2;

    int blk = blockIdx.x;
    int ntp = blk >= TILES;
    int tb  = blk - ntp*TILES;
    int base = tb*128; if (base > NN-128) base = NN-128;
    size_t nbase = (size_t)ntp*NN + base;

    // stage A = gelu(agg/den) -> fp16 smem (single-rounded)
    #pragma unroll 4
    for (int j = 0; j < 16; j++) {
        int idx = tid + j*256;
        int row = idx >> 5, c4 = idx & 31;
        size_t nrow = nbase + row;
        float4 v = ((const float4*)(g_agg + nrow*OUTF))[c4];
        float idn = 1.f / (g_den[nrow*HH + (c4 >> 3)] + 1e-16f);
        v.x *= idn; v.y *= idn; v.z *= idn; v.w *= idn;
        v.x = 0.5f*v.x*(1.f + erff(v.x*0.70710678118654752f));
        v.y = 0.5f*v.y*(1.f + erff(v.y*0.70710678118654752f));
        v.z = 0.5f*v.z*(1.f + erff(v.z*0.70710678118654752f));
        v.w = 0.5f*v.w*(1.f + erff(v.w*0.70710678118654752f));
        __half2 h01 = __floats2half2_rn(v.x, v.y);
        __half2 h23 = __floats2half2_rn(v.z, v.w);
        *(uint32_t*)(sm + A_HI_OFF + row*ROWB + c4*8)     = *reinterpret_cast<uint32_t*>(&h01);
        *(uint32_t*)(sm + A_HI_OFF + row*ROWB + c4*8 + 4) = *reinterpret_cast<uint32_t*>(&h23);
    }
    __syncthreads();
    copy_B(sm, 3, ntp, tid);
    __syncthreads();

    float acc[2][8][4];
    #pragma unroll
    for (int mt = 0; mt < 2; mt++)
        #pragma unroll
        for (int nt = 0; nt < 8; nt++) {
            int col = wn*64 + nt*8 + 2*(lane & 3);
            float b0 = ba[ntp*OUTF + col], b1 = ba[ntp*OUTF + col + 1];
            acc[mt][nt][0] = b0; acc[mt][nt][1] = b1;
            acc[mt][nt][2] = b0; acc[mt][nt][3] = b1;
        }
    gemm_1term(su, w, lane, acc);
    __syncthreads();   // all warps done reading A+B regions before reuse as S

    // acc -> S [128][136] f32 (spans whole 68KB smem)
    #pragma unroll
    for (int mt = 0; mt < 2; mt++)
        #pragma unroll
        for (int nt = 0; nt < 8; nt++) {
            int row = wm*32 + mt*16 + (lane >> 2);
            int col = wn*64 + nt*8 + 2*(lane & 3);
            *(float2*)(S + row*136 + col)     = make_float2(acc[mt][nt][0], acc[mt][nt][1]);
            *(float2*)(S + (row+8)*136 + col) = make_float2(acc[mt][nt][2], acc[mt][nt][3]);
        }
    __syncthreads();

    // skip blend
    float alpha = 1.f / (1.f + __expf(-skip[ntp]));
    float beta  = 1.f - alpha;
    #pragma unroll 4
    for (int i = tid; i < 128*128; i += 256) {
        int r = i >> 7, c = i & 127;
        S[r*136 + c] = alpha*S[r*136 + c] + beta*x[(nbase + r)*INF + c];
    }
    __syncthreads();

    // layernorm: warp w rows 16w..16w+15
    for (int rr = 0; rr < 16; rr++) {
        int r = w*16 + rr;
        float s1 = 0.f, s2 = 0.f;
        #pragma unroll
        for (int c = lane; c < OUTF; c += 32) { float v = S[r*136 + c]; s1 += v; s2 += v*v; }
        #pragma unroll
        for (int off = 16; off; off >>= 1) {
            s1 += __shfl_xor_sync(0xffffffffu, s1, off);
            s2 += __shfl_xor_sync(0xffffffffu, s2, off);
        }
        float mean = s1 * (1.f/OUTF);
        float var  = s2 * (1.f/OUTF) - mean*mean;
        float inv  = rsqrtf(var + 1e-5f);
        #pragma unroll
        for (int c = lane; c < OUTF; c += 32)
            out[(nbase + r)*OUTF + c] = (S[r*136 + c] - mean)*inv*lns[ntp*OUTF + c]
                                        + lnb[ntp*OUTF + c];
    }
}

// ---------------- launch ----------------
extern "C" void kernel_launch(void* const* d_in, const int* in_sizes, int n_in,
                              void* d_out, int out_size) {
    const float* x     = (const float*)d_in[0];
    const int*   ei    = (const int*)  d_in[1];
    const float* Wk    = (const float*)d_in[2];
    const float* bk    = (const float*)d_in[3];
    const float* Wq    = (const float*)d_in[4];
    const float* bq    = (const float*)d_in[5];
    const float* Wm    = (const float*)d_in[6];
    const float* bm    = (const float*)d_in[7];
    const float* Wa    = (const float*)d_in[8];
    const float* ba    = (const float*)d_in[9];
    const float* w_att = (const float*)d_in[10];
    const float* w_msg = (const float*)d_in[11];
    const float* mu    = (const float*)d_in[12];
    const float* skip  = (const float*)d_in[13];
    const float* lns   = (const float*)d_in[14];
    const float* lnb   = (const float*)d_in[15];
    float* out = (float*)d_out;

    cudaFuncSetAttribute(proj_mma_kernel, cudaFuncAttributeMaxDynamicSharedMemorySize, SMEM_TOT);
    cudaFuncSetAttribute(node_mma_kernel, cudaFuncAttributeMaxDynamicSharedMemorySize, SMEM_TOT);

    prep_fold<<<256, 256>>>(Wk, bk, Wm, bm, w_att, w_msg, mu);
    prep_pack<<<512, 256>>>(Wq, Wa);
    zero_hist<<<(2*NN + 255)/256, 256>>>();
    hist_kernel<<<(2*EE + 255)/256, 256>>>(ei);
    scan_blocks<<<(2*NN + 1023)/1024, 1024>>>();
    scan_tops<<<1, 512>>>();
    add_offs<<<(2*NN + 1023)/1024, 1024>>>();
    scatter_kernel<<<(2*EE + 255)/256, 256>>>(ei);
    proj_mma_kernel<<<2*TILES, 256, SMEM_TOT>>>(x, bq);
    edge_node_kernel<<<(2*NN*32 + 255)/256, 256>>>();
    node_mma_kernel<<<2*TILES, 256, SMEM_TOT>>>(x, ba, skip, lns, lnb, out);
}

// round 14
// speedup vs baseline: 1.2389x; 1.0408x over previous
#include <cuda_runtime.h>
#include <cuda_fp16.h>
#include <math.h>
#include <stdint.h>

#define NN 200000
#define EE 1000000
#define INF 128
#define OUTF 128
#define HH 4
#define DKK 32
#define TILES 1563            // ceil(NN/128)

// smem layout (bytes): rows padded to 272B (conflict-free LDSM)
#define ROWB 272
#define A_HI_OFF 0
#define B_OFF    34816        // B right after A_HI (1-term GEMMs everywhere)
#define SMEM_TOT 69632

// ---------------- scratch (device globals; no allocation) ----------------
__device__ __half g_KMh[(size_t)2*NN*2*OUTF];   // K/M interleaved fp16: [2N][2][128]
__device__ __half g_Qh [(size_t)2*NN*OUTF];     // fp16
__device__ __half g_aggh[(size_t)2*NN*OUTF];    // fp16 aggregation buffer
__device__ float  g_den[(size_t)2*NN*HH];       // f32 softmax denominators
__device__ float  g_WkA[2*INF*OUTF];
__device__ float  g_bkA[2*OUTF];
__device__ float  g_WmM[2*INF*OUTF];
__device__ float  g_bmM[2*OUTF];
// packed fp16 weights, W^T layout [o][k]: [mat(4)][type(2)][128*128]
__device__ __half g_Wh[(size_t)4*2*16384];
// exact-dst sorted edges: srcs only, grouped by destination node (d-major)
__device__ uint32_t g_srt[(size_t)2*EE];
__device__ int    g_hist[2*NN];
__device__ int    g_cursor[2*NN + 1];
__device__ int    g_cur2[2*NN];
__device__ int    g_bsum[512];
__device__ int    g_bsumx[512];

#define MMA16816F16(acc, A0,A1,A2,A3, B0,B1) \
  asm volatile("mma.sync.aligned.m16n8k16.row.col.f32.f16.f16.f32 " \
    "{%0,%1,%2,%3}, {%4,%5,%6,%7}, {%8,%9}, {%0,%1,%2,%3};" \
    : "+f"((acc)[0]), "+f"((acc)[1]), "+f"((acc)[2]), "+f"((acc)[3]) \
    : "r"(A0), "r"(A1), "r"(A2), "r"(A3), "r"(B0), "r"(B1))

#define LDSM4(r0,r1,r2,r3,addr) \
  asm volatile("ldmatrix.sync.aligned.m8n8.x4.shared.b16 {%0,%1,%2,%3}, [%4];" \
    : "=r"(r0), "=r"(r1), "=r"(r2), "=r"(r3) : "r"(addr))

__device__ __forceinline__ uint32_t smem_u32(const void* p) {
    uint32_t a;
    asm("{ .reg .u64 t; cvta.to.shared.u64 t, %1; cvt.u32.u64 %0, t; }" : "=r"(a) : "l"(p));
    return a;
}

// ---------------- prep: fold w_att/w_msg (+ mu*scale) into projection weights
__global__ void prep_fold(const float* __restrict__ Wk, const float* __restrict__ bk,
                          const float* __restrict__ Wm, const float* __restrict__ bm,
                          const float* __restrict__ w_att, const float* __restrict__ w_msg,
                          const float* __restrict__ mu) {
    int idx = blockIdx.x*blockDim.x + threadIdx.x;     // 65536
    const int total = 2*INF*OUTF;
    int m   = idx / total;
    int rem = idx - m*total;
    int t   = rem / (INF*OUTF);
    int io  = rem - t*(INF*OUTF);
    int i   = io / OUTF;
    int o   = io - i*OUTF;
    int h   = o >> 5, f = o & 31;

    const float* W = m ? Wm : Wk;
    const float* R = m ? w_msg : w_att;
    const float* wrow = W + ((size_t)t*INF + i)*OUTF + h*DKK;
    const float* rr   = R + (((size_t)t*HH + h)*DKK)*DKK + f;
    float s = 0.f;
    #pragma unroll
    for (int d = 0; d < DKK; d++) s += wrow[d] * rr[(size_t)d*DKK];
    float fold = m ? 1.f : mu[t*HH + h] * 0.17677669529663687f;   // mu / sqrt(DK)
    (m ? g_WmM : g_WkA)[(size_t)t*INF*OUTF + io] = s * fold;

    if (i == 0) {
        const float* b = m ? bm : bk;
        float sb = 0.f;
        #pragma unroll
        for (int d = 0; d < DKK; d++) sb += b[t*OUTF + h*DKK + d] * rr[(size_t)d*DKK];
        (m ? g_bmM : g_bkA)[t*OUTF + o] = sb * fold;
    }
}

// pack 4 matrices (Kfold, Mfold, Q, A) per type as W^T [o][k] fp16
__global__ void prep_pack(const float* __restrict__ Wq, const float* __restrict__ Wa) {
    int idx = blockIdx.x*blockDim.x + threadIdx.x;   // 131072
    int mat = idx >> 15;
    int rem = idx & 32767;
    int t   = rem >> 14;
    int ok  = rem & 16383;
    int o   = ok >> 7;
    int k   = ok & 127;
    const float* W = (mat==0) ? g_WkA : (mat==1) ? g_WmM : (mat==2) ? Wq : Wa;
    float v = W[((size_t)t*INF + k)*OUTF + o];
    g_Wh[(size_t)(mat*2 + t)*16384 + ok] = __float2half(v);
}

// ---------------- zero per-dst histogram ----------------
__global__ void zero_hist() {
    int i = blockIdx.x*blockDim.x + threadIdx.x;
    if (i < 2*NN) g_hist[i] = 0;
}

// ---------------- exact-dst bucketing: histogram -> 2-level scan -> scatter ----
__global__ void hist_kernel(const int* __restrict__ ei) {
    int i = blockIdx.x*blockDim.x + threadIdx.x;
    if (i >= 2*EE) return;
    int t = i >= EE;
    int e = i - t*EE;
    int dst = ei[(size_t)t*2*EE + EE + e];
    atomicAdd(&g_hist[(1-t)*NN + dst], 1);     // node key = d*NN + dst
}

__global__ void scan_blocks() {                // 391 blocks x 1024
    __shared__ int ss[1024];
    int tid = threadIdx.x;
    int gi = blockIdx.x*1024 + tid;
    int v = (gi < 2*NN) ? g_hist[gi] : 0;
    ss[tid] = v;
    __syncthreads();
    for (int off = 1; off < 1024; off <<= 1) {
        int u = (tid >= off) ? ss[tid-off] : 0;
        __syncthreads();
        ss[tid] += u;
        __syncthreads();
    }
    if (gi < 2*NN) g_cursor[gi] = ss[tid] - v;   // exclusive within block
    if (tid == 1023) g_bsum[blockIdx.x] = ss[1023];
}

__global__ void scan_tops() {                  // 1 block x 512 (covers 391 block sums)
    __shared__ int ss[512];
    int tid = threadIdx.x;
    int v = (tid < 391) ? g_bsum[tid] : 0;
    ss[tid] = v;
    __syncthreads();
    for (int off = 1; off < 512; off <<= 1) {
        int u = (tid >= off) ? ss[tid-off] : 0;
        __syncthreads();
        ss[tid] += u;
        __syncthreads();
    }
    g_bsumx[tid] = ss[tid] - v;                // exclusive
}

__global__ void add_offs() {                   // 391 blocks x 1024
    int tid = threadIdx.x;
    int gi = blockIdx.x*1024 + tid;
    if (gi < 2*NN) {
        int c = g_cursor[gi] + g_bsumx[blockIdx.x];
        g_cursor[gi] = c;
        g_cur2[gi]   = c;
    }
    if (gi == 0) g_cursor[2*NN] = 2*EE;
}

__global__ void scatter_kernel(const int* __restrict__ ei) {
    int i = blockIdx.x*blockDim.x + threadIdx.x;
    if (i >= 2*EE) return;
    int t = i >= EE;
    int e = i - t*EE;
    int src = ei[(size_t)t*2*EE + e];
    int dst = ei[(size_t)t*2*EE + EE + e];
    int pos = atomicAdd(&g_cur2[(1-t)*NN + dst], 1);
    g_srt[pos] = (uint32_t)src;
}

// copy one packed fp16 weight matrix (32KB) into the padded B buffer
__device__ __forceinline__ void copy_B(char* sm, int mat, int nt, int tid) {
    const uint4* src = (const uint4*)(g_Wh + (size_t)(mat*2 + nt) * 16384);
    #pragma unroll 2
    for (int i = tid; i < 2048; i += 256) {
        int row = i >> 4, chunk = i & 15;
        *(uint4*)(sm + B_OFF + row*ROWB + chunk*16) = src[i];
    }
}

// 1-term fp16 GEMM: acc += A*B
__device__ __forceinline__ void gemm_1term(uint32_t su, int w, int lane, float acc[2][8][4]) {
    int wm = w & 3, wn = w >> 2;
    int mat = lane >> 3, r8 = lane & 7;
    uint32_t aoff = (uint32_t)(wm*32 + (mat&1)*8 + r8)*ROWB + (mat>>1)*16;
    uint32_t boff = (uint32_t)(wn*64 + (mat>>1)*8 + r8)*ROWB + (mat&1)*16 + B_OFF;

    #pragma unroll
    for (int kk = 0; kk < 8; kk++) {
        uint32_t kb = kk*32;
        uint32_t A[2][4], B[8][2];
        #pragma unroll
        for (int mt = 0; mt < 2; mt++) {
            uint32_t ao = aoff + mt*16*ROWB + kb;
            LDSM4(A[mt][0], A[mt][1], A[mt][2], A[mt][3], su + A_HI_OFF + ao);
        }
        #pragma unroll
        for (int p = 0; p < 4; p++) {
            uint32_t bo = boff + p*16*ROWB + kb;
            LDSM4(B[2*p][0], B[2*p][1], B[2*p+1][0], B[2*p+1][1], su + bo);
        }
        #pragma unroll
        for (int mt = 0; mt < 2; mt++)
            #pragma unroll
            for (int nt = 0; nt < 8; nt++)
                MMA16816F16(acc[mt][nt], A[mt][0],A[mt][1],A[mt][2],A[mt][3], B[nt][0],B[nt][1]);
    }
}

// ---------------- proj: Ktr, Mtr, Q via 1-term mma.sync -> fp16 tables ----------------
__global__ void __launch_bounds__(256, 2) proj_mma_kernel(const float* __restrict__ x,
                                                          const float* __restrict__ bq) {
    extern __shared__ char sm[];
    uint32_t su = smem_u32(sm);
    int tid = threadIdx.x;
    int w = tid >> 5, lane = tid & 31;
    int wm = w & 3, wn = w >> 2;

    int blk = blockIdx.x;
    int ntp = blk >= TILES;
    int tb  = blk - ntp*TILES;
    int base = tb*128; if (base > NN-128) base = NN-128;
    size_t nbase = (size_t)ntp*NN + base;

    // stage A: x rows -> fp16 smem (single-rounded)
    #pragma unroll 4
    for (int j = 0; j < 16; j++) {
        int idx = tid + j*256;             // 4096 float4
        int row = idx >> 5, c4 = idx & 31;
        float4 v = ((const float4*)(x + (nbase + row)*INF))[c4];
        __half2 h01 = __floats2half2_rn(v.x, v.y);
        __half2 h23 = __floats2half2_rn(v.z, v.w);
        *(uint32_t*)(sm + A_HI_OFF + row*ROWB + c4*8)     = *reinterpret_cast<uint32_t*>(&h01);
        *(uint32_t*)(sm + A_HI_OFF + row*ROWB + c4*8 + 4) = *reinterpret_cast<uint32_t*>(&h23);
    }

    for (int m = 0; m < 3; m++) {
        __syncthreads();
        copy_B(sm, m, ntp, tid);
        __syncthreads();

        const float* bias = (m==0) ? g_bkA + ntp*OUTF
                          : (m==1) ? g_bmM + ntp*OUTF
                                   : bq    + ntp*OUTF;
        float acc[2][8][4];
        #pragma unroll
        for (int mt = 0; mt < 2; mt++)
            #pragma unroll
            for (int nt = 0; nt < 8; nt++) {
                int col = wn*64 + nt*8 + 2*(lane & 3);
                float b0 = bias[col], b1 = bias[col+1];
                acc[mt][nt][0] = b0; acc[mt][nt][1] = b1;
                acc[mt][nt][2] = b0; acc[mt][nt][3] = b1;
            }
        gemm_1term(su, w, lane, acc);
        __syncthreads();   // all warps done with B before staging reuses it

        // stage fp16 result into B buffer: 128 rows x 256B (+ ROWB pad)
        __half* H = (__half*)(sm + B_OFF);
        #pragma unroll
        for (int mt = 0; mt < 2; mt++)
            #pragma unroll
            for (int nt = 0; nt < 8; nt++) {
                int row = wm*32 + mt*16 + (lane >> 2);
                int col = wn*64 + nt*8 + 2*(lane & 3);
                *(__half2*)((char*)H + row*ROWB + col*2) =
                    __floats2half2_rn(acc[mt][nt][0], acc[mt][nt][1]);
                *(__half2*)((char*)H + (row+8)*ROWB + col*2) =
                    __floats2half2_rn(acc[mt][nt][2], acc[mt][nt][3]);
            }
        __syncthreads();

        // coalesced copy-out: 128 rows x 256B
        #pragma unroll
        for (int i = tid; i < 2048; i += 256) {
            int row = i >> 4, ch = i & 15;
            uint4 v = *(uint4*)((char*)H + row*ROWB + ch*16);
            __half* dst = (m == 2) ? g_Qh + (nbase + row)*OUTF + ch*8
                                   : g_KMh + ((nbase + row)*2 + m)*OUTF + ch*8;
            *(uint4*)dst = v;
        }
    }
}

// ---------------- edge pass: one warp per dst node, 2 edges/iter, 2-pair pipeline ----
__global__ void __launch_bounds__(256) edge_node_kernel() {
    int wid  = (blockIdx.x*blockDim.x + threadIdx.x) >> 5;   // node id [0, 2N)
    int lane = threadIdx.x & 31;
    if (wid >= 2*NN) return;
    int d = wid >= NN;
    int s = 1 - d;

    int start = g_cursor[wid];
    int end   = g_cursor[wid + 1];

    if (start == end) {   // empty segment: zeros
        ((uint2*)(g_aggh + (size_t)wid*OUTF))[lane] = make_uint2(0u, 0u);
        if ((lane & 7) == 0) g_den[(size_t)wid*HH + (lane >> 3)] = 0.f;
        return;
    }

    uint2 qv = ((const uint2*)(g_Qh + (size_t)wid*OUTF))[lane];
    float2 qa = __half22float2(*(const __half2*)&qv.x);
    float2 qb = __half22float2(*(const __half2*)&qv.y);

    float4 acc = make_float4(0.f, 0.f, 0.f, 0.f);
    float den = 0.f;

    const __half* KMbase = g_KMh + (size_t)s*NN*2*OUTF;

    // current pair in flight
    uint2 kc0, mc0, kc1, mc1;
    {
        int sc0 = (int)g_srt[start];
        const uint2* km0 = (const uint2*)(KMbase + (size_t)sc0*2*OUTF);
        kc0 = km0[lane]; mc0 = km0[32 + lane];
        if (start + 1 < end) {
            int sc1 = (int)g_srt[start + 1];
            const uint2* km1 = (const uint2*)(KMbase + (size_t)sc1*2*OUTF);
            kc1 = km1[lane]; mc1 = km1[32 + lane];
        }
    }

    for (int i = start; i < end; i += 2) {
        uint2 k0 = kc0, m0 = mc0, k1 = kc1, m1 = mc1;
        bool has1 = (i + 1 < end);
        // prefetch next pair
        if (i + 2 < end) {
            int sc0 = (int)g_srt[i + 2];
            const uint2* km0 = (const uint2*)(KMbase + (size_t)sc0*2*OUTF);
            kc0 = km0[lane]; mc0 = km0[32 + lane];
            if (i + 3 < end) {
                int sc1 = (int)g_srt[i + 3];
                const uint2* km1 = (const uint2*)(KMbase + (size_t)sc1*2*OUTF);
                kc1 = km1[lane]; mc1 = km1[32 + lane];
            }
        }

        // edge i
        {
            float2 ka = __half22float2(*(const __half2*)&k0.x);
            float2 kb = __half22float2(*(const __half2*)&k0.y);
            float p = ka.x*qa.x + ka.y*qa.y + kb.x*qb.x + kb.y*qb.y;
            p += __shfl_down_sync(0xffffffffu, p, 4, 8);
            p += __shfl_down_sync(0xffffffffu, p, 2, 8);
            p += __shfl_down_sync(0xffffffffu, p, 1, 8);
            float att = __shfl_sync(0xffffffffu, p, 0, 8);
            float ev  = __expf(att);
            float2 ma = __half22float2(*(const __half2*)&m0.x);
            float2 mb = __half22float2(*(const __half2*)&m0.y);
            acc.x += ma.x*ev; acc.y += ma.y*ev;
            acc.z += mb.x*ev; acc.w += mb.y*ev;
            den += ev;
        }
        // edge i+1
        if (has1) {
            float2 ka = __half22float2(*(const __half2*)&k1.x);
            float2 kb = __half22float2(*(const __half2*)&k1.y);
            float p = ka.x*qa.x + ka.y*qa.y + kb.x*qb.x + kb.y*qb.y;
            p += __shfl_down_sync(0xffffffffu, p, 4, 8);
            p += __shfl_down_sync(0xffffffffu, p, 2, 8);
            p += __shfl_down_sync(0xffffffffu, p, 1, 8);
            float att = __shfl_sync(0xffffffffu, p, 0, 8);
            float ev  = __expf(att);
            float2 ma = __half22float2(*(const __half2*)&m1.x);
            float2 mb = __half22float2(*(const __half2*)&m1.y);
            acc.x += ma.x*ev; acc.y += ma.y*ev;
            acc.z += mb.x*ev; acc.w += mb.y*ev;
            den += ev;
        }
    }

    // fp16 agg write (coalesced 256B/row)
    __half2 o01 = __floats2half2_rn(acc.x, acc.y);
    __half2 o23 = __floats2half2_rn(acc.z, acc.w);
    uint2 ov;
    ov.x = *reinterpret_cast<uint32_t*>(&o01);
    ov.y = *reinterpret_cast<uint32_t*>(&o23);
    ((uint2*)(g_aggh + (size_t)wid*OUTF))[lane] = ov;
    if ((lane & 7) == 0)
        g_den[(size_t)wid*HH + (lane >> 3)] = den;
}

// ---------------- node pass: gelu(agg/den) -> 1-term mma GEMM -> skip + LN ------
__global__ void __launch_bounds__(256, 2) node_mma_kernel(const float* __restrict__ x,
                                                          const float* __restrict__ ba,
                                                          const float* __restrict__ skip,
                                                          const float* __restrict__ lns,
                                                          const float* __restrict__ lnb,
                                                          float* __restrict__ out) {
    extern __shared__ char sm[];
    uint32_t su = smem_u32(sm);
    float* S = (float*)sm;        // reuse full smem after GEMM: [128][136] f32 = 69632B
    int tid = threadIdx.x;
    int w = tid >> 5, lane = tid & 31;
    int wm = w & 3, wn = w >> 2;

    int blk = blockIdx.x;
    int ntp = blk >= TILES;
    int tb  = blk - ntp*TILES;
    int base = tb*128; if (base > NN-128) base = NN-128;
    size_t nbase = (size_t)ntp*NN + base;

    // stage A = gelu(agg/den) -> fp16 smem
    #pragma unroll 4
    for (int j = 0; j < 16; j++) {
        int idx = tid + j*256;
        int row = idx >> 5, c4 = idx & 31;
        size_t nrow = nbase + row;
        uint2 av = ((const uint2*)(g_aggh + nrow*OUTF))[c4];
        float2 a01 = __half22float2(*(const __half2*)&av.x);
        float2 a23 = __half22float2(*(const __half2*)&av.y);
        float idn = 1.f / (g_den[nrow*HH + (c4 >> 3)] + 1e-16f);
        float4 v;
        v.x = a01.x*idn; v.y = a01.y*idn; v.z = a23.x*idn; v.w = a23.y*idn;
        v.x = 0.5f*v.x*(1.f + erff(v.x*0.70710678118654752f));
        v.y = 0.5f*v.y*(1.f + erff(v.y*0.70710678118654752f));
        v.z = 0.5f*v.z*(1.f + erff(v.z*0.70710678118654752f));
        v.w = 0.5f*v.w*(1.f + erff(v.w*0.70710678118654752f));
        __half2 h01 = __floats2half2_rn(v.x, v.y);
        __half2 h23 = __floats2half2_rn(v.z, v.w);
        *(uint32_t*)(sm + A_HI_OFF + row*ROWB + c4*8)     = *reinterpret_cast<uint32_t*>(&h01);
        *(uint32_t*)(sm + A_HI_OFF + row*ROWB + c4*8 + 4) = *reinterpret_cast<uint32_t*>(&h23);
    }
    __syncthreads();
    copy_B(sm, 3, ntp, tid);
    __syncthreads();

    float acc[2][8][4];
    #pragma unroll
    for (int mt = 0; mt < 2; mt++)
        #pragma unroll
        for (int nt = 0; nt < 8; nt++) {
            int col = wn*64 + nt*8 + 2*(lane & 3);
            float b0 = ba[ntp*OUTF + col], b1 = ba[ntp*OUTF + col + 1];
            acc[mt][nt][0] = b0; acc[mt][nt][1] = b1;
            acc[mt][nt][2] = b0; acc[mt][nt][3] = b1;
        }
    gemm_1term(su, w, lane, acc);
    __syncthreads();   // all warps done reading A+B regions before reuse as S

    // acc -> S [128][136] f32 (spans whole smem)
    #pragma unroll
    for (int mt = 0; mt < 2; mt++)
        #pragma unroll
        for (int nt = 0; nt < 8; nt++) {
            int row = wm*32 + mt*16 + (lane >> 2);
            int col = wn*64 + nt*8 + 2*(lane & 3);
            *(float2*)(S + row*136 + col)     = make_float2(acc[mt][nt][0], acc[mt][nt][1]);
            *(float2*)(S + (row+8)*136 + col) = make_float2(acc[mt][nt][2], acc[mt][nt][3]);
        }
    __syncthreads();

    // skip blend
    float alpha = 1.f / (1.f + __expf(-skip[ntp]));
    float beta  = 1.f - alpha;
    #pragma unroll 4
    for (int i = tid; i < 128*128; i += 256) {
        int r = i >> 7, c = i & 127;
        S[r*136 + c] = alpha*S[r*136 + c] + beta*x[(nbase + r)*INF + c];
    }
    __syncthreads();

    // layernorm: warp w rows 16w..16w+15
    for (int rr = 0; rr < 16; rr++) {
        int r = w*16 + rr;
        float s1 = 0.f, s2 = 0.f;
        #pragma unroll
        for (int c = lane; c < OUTF; c += 32) { float v = S[r*136 + c]; s1 += v; s2 += v*v; }
        #pragma unroll
        for (int off = 16; off; off >>= 1) {
            s1 += __shfl_xor_sync(0xffffffffu, s1, off);
            s2 += __shfl_xor_sync(0xffffffffu, s2, off);
        }
        float mean = s1 * (1.f/OUTF);
        float var  = s2 * (1.f/OUTF) - mean*mean;
        float inv  = rsqrtf(var + 1e-5f);
        #pragma unroll
        for (int c = lane; c < OUTF; c += 32)
            out[(nbase + r)*OUTF + c] = (S[r*136 + c] - mean)*inv*lns[ntp*OUTF + c]
                                        + lnb[ntp*OUTF + c];
    }
}

// ---------------- launch ----------------
extern "C" void kernel_launch(void* const* d_in, const int* in_sizes, int n_in,
                              void* d_out, int out_size) {
    const float* x     = (const float*)d_in[0];
    const int*   ei    = (const int*)  d_in[1];
    const float* Wk    = (const float*)d_in[2];
    const float* bk    = (const float*)d_in[3];
    const float* Wq    = (const float*)d_in[4];
    const float* bq    = (const float*)d_in[5];
    const float* Wm    = (const float*)d_in[6];
    const float* bm    = (const float*)d_in[7];
    const float* Wa    = (const float*)d_in[8];
    const float* ba    = (const float*)d_in[9];
    const float* w_att = (const float*)d_in[10];
    const float* w_msg = (const float*)d_in[11];
    const float* mu    = (const float*)d_in[12];
    const float* skip  = (const float*)d_in[13];
    const float* lns   = (const float*)d_in[14];
    const float* lnb   = (const float*)d_in[15];
    float* out = (float*)d_out;

    cudaFuncSetAttribute(proj_mma_kernel, cudaFuncAttributeMaxDynamicSharedMemorySize, SMEM_TOT);
    cudaFuncSetAttribute(node_mma_kernel, cudaFuncAttributeMaxDynamicSharedMemorySize, SMEM_TOT);

    prep_fold<<<256, 256>>>(Wk, bk, Wm, bm, w_att, w_msg, mu);
    prep_pack<<<512, 256>>>(Wq, Wa);
    zero_hist<<<(2*NN + 255)/256, 256>>>();
    hist_kernel<<<(2*EE + 255)/256, 256>>>(ei);
    scan_blocks<<<(2*NN + 1023)/1024, 1024>>>();
    scan_tops<<<1, 512>>>();
    add_offs<<<(2*NN + 1023)/1024, 1024>>>();
    scatter_kernel<<<(2*EE + 255)/256, 256>>>(ei);
    proj_mma_kernel<<<2*TILES, 256, SMEM_TOT>>>(x, bq);
    edge_node_kernel<<<(2*NN*32 + 255)/256, 256>>>();
    node_mma_kernel<<<2*TILES, 256, SMEM_TOT>>>(x, ba, skip, lns, lnb, out);
}